// round 10
// baseline (speedup 1.0000x reference)
#include <cuda_runtime.h>
#include <cstdint>

// ============================================================================
// AdditiveAttention: out = softmax_mask( sum_h tanh(Q@Wq + K@Wk) * wv ) @ V
// B=16, Q=128, K=128, D=512, H=512
//  kernel 1 (sgemm_proj): Qp/Kp projections — packed fma.rn.f32x2 micro-kernel
//      (2 MACs per issue slot; B kept pre-packed in smem, A broadcast by mov.b64)
//  kernel 2 (score_kernel): persistent 148 blocks x 512 thr, 256 tasks of
//      (batch, 16 q-rows, h-half). Partial scores to 2 disjoint gmem buffers.
//  kernel 3 (softmax_av): grid 128 x 512 thr: sum halves, masked softmax, AV.
// ============================================================================

#define BDIM 16
#define QDIM 128
#define KDIM 128
#define DDIM 512
#define HDIM 512
#define NTASKS 256          // 16 b * 8 qt * 2 h-halves
#define NBLOCKS 148

typedef unsigned long long u64;

__device__ float g_Qp[BDIM * QDIM * HDIM];     // 4 MB
__device__ float g_Kp[BDIM * KDIM * HDIM];     // 4 MB
__device__ float g_S[2][BDIM][QDIM][KDIM];     // partial scores, 2 MB
__device__ int   g_counter;                    // zero-init; self-reset at end
__device__ int   g_done;

__device__ __forceinline__ float tanh_fast(float x) {
    float y;
    asm("tanh.approx.f32 %0, %1;" : "=f"(y) : "f"(x));
    return y;
}
__device__ __forceinline__ u64 bcast2(float x) {
    u64 r;
    asm("mov.b64 %0, {%1, %1};" : "=l"(r) : "f"(x));
    return r;
}
__device__ __forceinline__ void ffma2(u64& d, u64 a, u64 b) {
    asm("fma.rn.f32x2 %0, %1, %2, %0;" : "+l"(d) : "l"(a), "l"(b));
}

// ----------------------------------------------------------------------------
// Kernel 1: C[M,N] = A[M,K] * W[K,N]   M=2048, K=512, N=512 (x2 via blockIdx.z)
// 128x128 tile, BK=16, 256 threads, 8x8 micro-tile as 8x(4 f32x2) FFMA2.
// ----------------------------------------------------------------------------
__global__ __launch_bounds__(256, 1) void sgemm_proj(
    const float* __restrict__ Aq, const float* __restrict__ Ak,
    const float* __restrict__ Wq, const float* __restrict__ Wk)
{
    const int K = DDIM;
    const int N = HDIM;

    const float* A = blockIdx.z ? Ak : Aq;
    const float* W = blockIdx.z ? Wk : Wq;
    float* C = blockIdx.z ? g_Kp : g_Qp;

    __shared__ __align__(16) float As[16][132];   // transposed: As[k][m]
    __shared__ __align__(16) float Ws[16][128];   // Ws[k][n] (pairs are packed)

    const int tid = threadIdx.x;
    const int tx = tid & 15;
    const int ty = tid >> 4;
    const int m0 = blockIdx.y * 128;
    const int n0 = blockIdx.x * 128;

    const int arow = tid >> 2;
    const int ac   = (tid & 3) << 2;
    const int wk   = tid >> 5;
    const int wn   = (tid & 31) << 2;

    u64 acc2[8][4];
#pragma unroll
    for (int i = 0; i < 8; i++)
#pragma unroll
        for (int j = 0; j < 4; j++) acc2[i][j] = 0ull;

    float4 pa0, pa1, pw0, pw1;

    pa0 = *(const float4*)&A[(m0 + arow) * K + 0 + ac];
    pa1 = *(const float4*)&A[(m0 + arow + 64) * K + 0 + ac];
    pw0 = *(const float4*)&W[(0 + wk) * N + n0 + wn];
    pw1 = *(const float4*)&W[(0 + wk + 8) * N + n0 + wn];

    As[ac + 0][arow] = pa0.x; As[ac + 1][arow] = pa0.y;
    As[ac + 2][arow] = pa0.z; As[ac + 3][arow] = pa0.w;
    As[ac + 0][arow + 64] = pa1.x; As[ac + 1][arow + 64] = pa1.y;
    As[ac + 2][arow + 64] = pa1.z; As[ac + 3][arow + 64] = pa1.w;
    *(float4*)&Ws[wk][wn] = pw0;
    *(float4*)&Ws[wk + 8][wn] = pw1;
    __syncthreads();

    const int NIT = K / 16;   // 32
    for (int it = 0; it < NIT; ++it) {
        if (it + 1 < NIT) {
            const int kt = (it + 1) * 16;
            pa0 = *(const float4*)&A[(m0 + arow) * K + kt + ac];
            pa1 = *(const float4*)&A[(m0 + arow + 64) * K + kt + ac];
            pw0 = *(const float4*)&W[(kt + wk) * N + n0 + wn];
            pw1 = *(const float4*)&W[(kt + wk + 8) * N + n0 + wn];
        }
#pragma unroll
        for (int kk = 0; kk < 16; ++kk) {
            float a[8];
            *(float4*)&a[0] = *(const float4*)&As[kk][ty * 8];
            *(float4*)&a[4] = *(const float4*)&As[kk][ty * 8 + 4];
            // B pairs are adjacent in smem: read pre-packed 64-bit lanes.
            u64 b2[4];
            const ulonglong2 bl0 = *(const ulonglong2*)&Ws[kk][tx * 8];
            const ulonglong2 bl1 = *(const ulonglong2*)&Ws[kk][tx * 8 + 4];
            b2[0] = bl0.x; b2[1] = bl0.y; b2[2] = bl1.x; b2[3] = bl1.y;
#pragma unroll
            for (int i = 0; i < 8; i++) {
                const u64 a2 = bcast2(a[i]);
#pragma unroll
                for (int j = 0; j < 4; j++)
                    ffma2(acc2[i][j], a2, b2[j]);
            }
        }
        __syncthreads();
        if (it + 1 < NIT) {
            As[ac + 0][arow] = pa0.x; As[ac + 1][arow] = pa0.y;
            As[ac + 2][arow] = pa0.z; As[ac + 3][arow] = pa0.w;
            As[ac + 0][arow + 64] = pa1.x; As[ac + 1][arow + 64] = pa1.y;
            As[ac + 2][arow + 64] = pa1.z; As[ac + 3][arow + 64] = pa1.w;
            *(float4*)&Ws[wk][wn] = pw0;
            *(float4*)&Ws[wk + 8][wn] = pw1;
            __syncthreads();
        }
    }

#pragma unroll
    for (int i = 0; i < 8; i++) {
        u64* crow = (u64*)&C[(m0 + ty * 8 + i) * N + n0 + tx * 8];
#pragma unroll
        for (int j = 0; j < 4; j++) crow[j] = acc2[i][j];
    }
}

// ----------------------------------------------------------------------------
// Kernel 2: partial scores. Task t: hh = t&1, b = (t>>1)&15, qt = t>>5.
// S_partial[hh][b][qt*16+w][k] = sum_{h in half} tanh(q+k)*wv[h]
// 512 threads, 16 warps: warp w owns q-row w; lane tk owns k in {tk+32j}.
// 32-k groups with base >= vlen skipped; K loads bounded by kmax.
// ----------------------------------------------------------------------------
#define HC 64
#define KS_STRIDE 68   // 68 % 32 == 4 -> conflict-free LDS.128
#define POOL_FLOATS (128 * KS_STRIDE + 16 * KS_STRIDE + HDIM)   // 10304 = 41.2KB

__global__ __launch_bounds__(512, 1) void score_kernel(
    const int* __restrict__ valid_lens,
    const float* __restrict__ wv)
{
    const int tid = threadIdx.x;
    const int tk  = tid & 31;
    const int w   = tid >> 5;         // 0..15 -> q-row within tile

    __shared__ __align__(16) float pool[POOL_FLOATS];
    float (*Ks)[KS_STRIDE] = (float(*)[KS_STRIDE])&pool[0];                 // 128x68
    float (*Qs)[KS_STRIDE] = (float(*)[KS_STRIDE])&pool[128 * KS_STRIDE];   // 16x68
    float* wvs = &pool[144 * KS_STRIDE];                                    // 512
    __shared__ int s_task;

    if (tid < 128)
        *(float4*)&wvs[tid * 4] = *(const float4*)&wv[tid * 4];

    const int kq_row = tid >> 4;      // 0..31 (+32*i)
    const int kq_c4  = tid & 15;
    const int q_row  = tid >> 4;      // 0..15 for tid<256
    const int q_c4   = tid & 15;

    for (;;) {
        if (tid == 0) s_task = atomicAdd(&g_counter, 1);
        __syncthreads();
        const int t = s_task;
        if (t >= NTASKS) break;

        const int hh = t & 1;
        const int b  = (t >> 1) & 15;
        const int qt = t >> 5;                 // 0..7
        const int vlen = valid_lens[b];
        const int kmax = min(KDIM, (vlen + 31) & ~31);
        const bool act1 = (32 < vlen);
        const bool act2 = (64 < vlen);
        const bool act3 = (96 < vlen);
        const int hbase = hh * (HDIM / 2);     // 0 or 256

        const float* Qp = g_Qp + (b * QDIM + qt * 16) * HDIM;
        const float* Kp = g_Kp + b * KDIM * HDIM;

        float4 pk[4];
        float4 pq;

#pragma unroll
        for (int i = 0; i < 4; i++)
            if (kq_row + 32 * i < kmax)
                pk[i] = *(const float4*)&Kp[(kq_row + 32 * i) * HDIM + hbase + kq_c4 * 4];
        if (tid < 256)
            pq = *(const float4*)&Qp[q_row * HDIM + hbase + q_c4 * 4];

#pragma unroll
        for (int i = 0; i < 4; i++)
            if (kq_row + 32 * i < kmax)
                *(float4*)&Ks[kq_row + 32 * i][kq_c4 * 4] = pk[i];
        if (tid < 256)
            *(float4*)&Qs[q_row][q_c4 * 4] = pq;
        __syncthreads();

        float s0 = 0.0f, s1 = 0.0f, s2 = 0.0f, s3 = 0.0f;

        const int NCH = (HDIM / 2) / HC;   // 4
        for (int hc = 0; hc < NCH; ++hc) {
            const int h0 = hbase + hc * HC;
            if (hc + 1 < NCH) {
                const int hn = h0 + HC;
#pragma unroll
                for (int i = 0; i < 4; i++)
                    if (kq_row + 32 * i < kmax)
                        pk[i] = *(const float4*)&Kp[(kq_row + 32 * i) * HDIM + hn + kq_c4 * 4];
                if (tid < 256)
                    pq = *(const float4*)&Qp[q_row * HDIM + hn + q_c4 * 4];
            }

#pragma unroll
            for (int h4 = 0; h4 < HC / 4; ++h4) {
                const float4 w4 = *(const float4*)&wvs[h0 + h4 * 4];
                const float4 qa = *(const float4*)&Qs[w][h4 * 4];
                {
                    const float4 kv = *(const float4*)&Ks[tk][h4 * 4];
                    s0 = fmaf(tanh_fast(qa.x + kv.x), w4.x, s0);
                    s0 = fmaf(tanh_fast(qa.y + kv.y), w4.y, s0);
                    s0 = fmaf(tanh_fast(qa.z + kv.z), w4.z, s0);
                    s0 = fmaf(tanh_fast(qa.w + kv.w), w4.w, s0);
                }
                if (act1) {
                    const float4 kv = *(const float4*)&Ks[tk + 32][h4 * 4];
                    s1 = fmaf(tanh_fast(qa.x + kv.x), w4.x, s1);
                    s1 = fmaf(tanh_fast(qa.y + kv.y), w4.y, s1);
                    s1 = fmaf(tanh_fast(qa.z + kv.z), w4.z, s1);
                    s1 = fmaf(tanh_fast(qa.w + kv.w), w4.w, s1);
                }
                if (act2) {
                    const float4 kv = *(const float4*)&Ks[tk + 64][h4 * 4];
                    s2 = fmaf(tanh_fast(qa.x + kv.x), w4.x, s2);
                    s2 = fmaf(tanh_fast(qa.y + kv.y), w4.y, s2);
                    s2 = fmaf(tanh_fast(qa.z + kv.z), w4.z, s2);
                    s2 = fmaf(tanh_fast(qa.w + kv.w), w4.w, s2);
                }
                if (act3) {
                    const float4 kv = *(const float4*)&Ks[tk + 96][h4 * 4];
                    s3 = fmaf(tanh_fast(qa.x + kv.x), w4.x, s3);
                    s3 = fmaf(tanh_fast(qa.y + kv.y), w4.y, s3);
                    s3 = fmaf(tanh_fast(qa.z + kv.z), w4.z, s3);
                    s3 = fmaf(tanh_fast(qa.w + kv.w), w4.w, s3);
                }
            }
            __syncthreads();
            if (hc + 1 < NCH) {
#pragma unroll
                for (int i = 0; i < 4; i++)
                    if (kq_row + 32 * i < kmax)
                        *(float4*)&Ks[kq_row + 32 * i][kq_c4 * 4] = pk[i];
                if (tid < 256)
                    *(float4*)&Qs[q_row][q_c4 * 4] = pq;
                __syncthreads();
            }
        }

        float* Sp = &g_S[hh][b][qt * 16 + w][0];
        Sp[tk] = s0;
        if (act1) Sp[tk + 32] = s1;
        if (act2) Sp[tk + 64] = s2;
        if (act3) Sp[tk + 96] = s3;
    }

    if (tid == 0) {
        __threadfence();
        const int d = atomicAdd(&g_done, 1);
        if (d == NBLOCKS - 1) { g_counter = 0; g_done = 0; }
    }
}

// ----------------------------------------------------------------------------
// Kernel 3: sum partials, masked softmax, attn@V.
// grid (8 qt, 16 b) x 512 thr. Warp w: q-row w. Thread tid: d-column tid.
// ----------------------------------------------------------------------------
__global__ __launch_bounds__(512, 1) void softmax_av(
    const float* __restrict__ values,
    const int* __restrict__ valid_lens,
    float* __restrict__ out)
{
    const int b  = blockIdx.y;
    const int qt = blockIdx.x;
    const int tid = threadIdx.x;
    const int tk  = tid & 31;
    const int w   = tid >> 5;

    __shared__ __align__(16) float attnT[128][20];

    const int vlen = valid_lens[b];
    const int kmax = min(KDIM, (vlen + 31) & ~31);

    const float* S0 = &g_S[0][b][qt * 16 + w][0];
    const float* S1 = &g_S[1][b][qt * 16 + w][0];

    float s[4];
#pragma unroll
    for (int j = 0; j < 4; j++) {
        const int k = tk + 32 * j;
        s[j] = (k < kmax) ? (S0[k] + S1[k]) : -1e6f;
        if (k >= vlen) s[j] = -1e6f;
    }

    float m = fmaxf(fmaxf(s[0], s[1]), fmaxf(s[2], s[3]));
#pragma unroll
    for (int off = 16; off > 0; off >>= 1)
        m = fmaxf(m, __shfl_xor_sync(0xFFFFFFFFu, m, off));
    float sum = 0.0f;
#pragma unroll
    for (int j = 0; j < 4; j++) {
        s[j] = __expf(s[j] - m);
        sum += s[j];
    }
#pragma unroll
    for (int off = 16; off > 0; off >>= 1)
        sum += __shfl_xor_sync(0xFFFFFFFFu, sum, off);
    const float rs = 1.0f / sum;
#pragma unroll
    for (int j = 0; j < 4; j++)
        attnT[tk + 32 * j][w] = s[j] * rs;
    __syncthreads();

    const int d = tid;
    const float* Vb = values + b * KDIM * DDIM + d;
    float acc[16];
#pragma unroll
    for (int q = 0; q < 16; q++) acc[q] = 0.0f;

    for (int k = 0; k < kmax; ++k) {
        const float v = Vb[k * DDIM];
        float a[16];
        *(float4*)&a[0]  = *(const float4*)&attnT[k][0];
        *(float4*)&a[4]  = *(const float4*)&attnT[k][4];
        *(float4*)&a[8]  = *(const float4*)&attnT[k][8];
        *(float4*)&a[12] = *(const float4*)&attnT[k][12];
#pragma unroll
        for (int q = 0; q < 16; q++)
            acc[q] = fmaf(a[q], v, acc[q]);
    }

    float* Ob = out + (b * QDIM + qt * 16) * DDIM + d;
#pragma unroll
    for (int q = 0; q < 16; q++)
        Ob[q * DDIM] = acc[q];
}

// ----------------------------------------------------------------------------
extern "C" void kernel_launch(void* const* d_in, const int* in_sizes, int n_in,
                              void* d_out, int out_size)
{
    const float* queries    = (const float*)d_in[0];
    const float* keys       = (const float*)d_in[1];
    const float* values     = (const float*)d_in[2];
    const int*   valid_lens = (const int*)d_in[3];
    const float* Wq         = (const float*)d_in[4];
    const float* Wk         = (const float*)d_in[5];
    const float* wv         = (const float*)d_in[6];
    float* out = (float*)d_out;

    sgemm_proj<<<dim3(4, 16, 2), 256>>>(queries, keys, Wq, Wk);
    score_kernel<<<NBLOCKS, 512>>>(valid_lens, wv);
    softmax_av<<<dim3(8, 16), 512>>>(values, valid_lens, out);
}

// round 11
// speedup vs baseline: 1.1634x; 1.1634x over previous
#include <cuda_runtime.h>
#include <cuda_bf16.h>
#include <cstdint>

// ============================================================================
// AdditiveAttention: out = softmax_mask( sum_h tanh(Q@Wq + K@Wk) * wv ) @ V
// B=16, Q=128, K=128, D=512, H=512
//  prep_a / prep_w : fp32 -> bf16 (hi, lo) split copies; W also transposed
//  bf16_gemm      : Qp/Kp = A@W via mma.sync m16n8k16 bf16, 3-term split
//  score_kernel   : persistent 148x512, 256 tasks (b, 16 q-rows, h-half)
//  softmax_av     : sum halves, masked softmax, AV
// ============================================================================

#define BDIM 16
#define QDIM 128
#define KDIM 128
#define DDIM 512
#define HDIM 512
#define NTASKS 256
#define NBLOCKS 148

__device__ float g_Qp[BDIM * QDIM * HDIM];     // 4 MB
__device__ float g_Kp[BDIM * KDIM * HDIM];     // 4 MB
__device__ float g_S[2][BDIM][QDIM][KDIM];     // partial scores, 2 MB
__device__ int   g_counter;
__device__ int   g_done;

// bf16-split operands (ushort = raw bf16 bits)
__device__ unsigned short g_Ah[2][2048 * 512];   // A hi   (z=0: queries, 1: keys)
__device__ unsigned short g_Al[2][2048 * 512];   // A lo
__device__ unsigned short g_Bth[2][512 * 512];   // W^T hi : [n][k]
__device__ unsigned short g_Btl[2][512 * 512];   // W^T lo

__device__ __forceinline__ float tanh_fast(float x) {
    float y;
    asm("tanh.approx.f32 %0, %1;" : "=f"(y) : "f"(x));
    return y;
}
__device__ __forceinline__ void bf16_split(float x, unsigned short& hi, unsigned short& lo) {
    __nv_bfloat16 h = __float2bfloat16_rn(x);
    __nv_bfloat16 l = __float2bfloat16_rn(x - __bfloat162float(h));
    hi = __bfloat16_as_ushort(h);
    lo = __bfloat16_as_ushort(l);
}
__device__ __forceinline__ void ldsm_x4(uint32_t* r, uint32_t addr) {
    asm volatile("ldmatrix.sync.aligned.m8n8.x4.shared.b16 {%0,%1,%2,%3}, [%4];"
        : "=r"(r[0]), "=r"(r[1]), "=r"(r[2]), "=r"(r[3]) : "r"(addr));
}
__device__ __forceinline__ void mma_bf16(float* c, const uint32_t* a, const uint32_t* b) {
    asm volatile("mma.sync.aligned.m16n8k16.row.col.f32.bf16.bf16.f32 "
        "{%0,%1,%2,%3}, {%4,%5,%6,%7}, {%8,%9}, {%0,%1,%2,%3};"
        : "+f"(c[0]), "+f"(c[1]), "+f"(c[2]), "+f"(c[3])
        : "r"(a[0]), "r"(a[1]), "r"(a[2]), "r"(a[3]), "r"(b[0]), "r"(b[1]));
}

// ----------------------------------------------------------------------------
// prep_a: split A (queries/keys) into bf16 hi/lo, row-major [m][k].
// grid (1024, 2) x 256; one float4 per thread.
// ----------------------------------------------------------------------------
__global__ void prep_a(const float* __restrict__ Aq, const float* __restrict__ Ak)
{
    const int z = blockIdx.y;
    const float* A = z ? Ak : Aq;
    const int idx = blockIdx.x * 256 + threadIdx.x;   // float4 index, < 262144
    const float4 v = ((const float4*)A)[idx];
    ushort4 h, l;
    bf16_split(v.x, h.x, l.x);
    bf16_split(v.y, h.y, l.y);
    bf16_split(v.z, h.z, l.z);
    bf16_split(v.w, h.w, l.w);
    ((ushort4*)g_Ah[z])[idx] = h;
    ((ushort4*)g_Al[z])[idx] = l;
}

// ----------------------------------------------------------------------------
// prep_w: split + transpose W [k][n] -> Bt [n][k] bf16 hi/lo.
// grid (16, 16, 2) x (32, 32); smem tile transpose.
// ----------------------------------------------------------------------------
__global__ void prep_w(const float* __restrict__ Wq, const float* __restrict__ Wk)
{
    __shared__ float tile[32][33];
    const int z = blockIdx.z;
    const float* W = z ? Wk : Wq;
    const int k = blockIdx.y * 32 + threadIdx.y;
    const int n = blockIdx.x * 32 + threadIdx.x;
    tile[threadIdx.y][threadIdx.x] = W[k * 512 + n];
    __syncthreads();
    const int on = blockIdx.x * 32 + threadIdx.y;
    const int ok = blockIdx.y * 32 + threadIdx.x;
    unsigned short hi, lo;
    bf16_split(tile[threadIdx.x][threadIdx.y], hi, lo);
    g_Bth[z][on * 512 + ok] = hi;
    g_Btl[z][on * 512 + ok] = lo;
}

// ----------------------------------------------------------------------------
// bf16_gemm: C[2048,512] = A@W per z. 128x128 tile, KC=32, 256 thr (8 warps
// as 4x2), warp tile 32x64 (2 m-tiles x 8 n-tiles of m16n8k16).
// 3-term split accumulation: AhBh + AhBl + AlBh.
// ----------------------------------------------------------------------------
#define KC 32
#define AST 40   // smem row stride in bf16 elems (32 + 8 pad): 80B -> conflict-free ldmatrix

__global__ __launch_bounds__(256, 1) void bf16_gemm()
{
    const int z  = blockIdx.z;
    const int m0 = blockIdx.y * 128;
    const int n0 = blockIdx.x * 128;

    const unsigned short* Ah = g_Ah[z];
    const unsigned short* Al = g_Al[z];
    const unsigned short* Bh = g_Bth[z];
    const unsigned short* Bl = g_Btl[z];
    float* C = z ? g_Kp : g_Qp;

    __shared__ __align__(16) unsigned short sAh[128 * AST];
    __shared__ __align__(16) unsigned short sAl[128 * AST];
    __shared__ __align__(16) unsigned short sBh[128 * AST];
    __shared__ __align__(16) unsigned short sBl[128 * AST];

    const int tid  = threadIdx.x;
    const int lane = tid & 31;
    const int wid  = tid >> 5;
    const int warp_m = wid & 3;    // 0..3 -> m offset warp_m*32
    const int warp_n = wid >> 2;   // 0..1 -> n offset warp_n*64

    // loader: row lr (0..127), 16-elem column segment lc (0 or 16)
    const int lr = tid >> 1;
    const int lc = (tid & 1) * 16;

    // ldmatrix per-lane offsets (bytes)
    const int grp = lane >> 3, l8 = lane & 7;
    const uint32_t sAh_b = (uint32_t)__cvta_generic_to_shared(sAh);
    const uint32_t sAl_b = (uint32_t)__cvta_generic_to_shared(sAl);
    const uint32_t sBh_b = (uint32_t)__cvta_generic_to_shared(sBh);
    const uint32_t sBl_b = (uint32_t)__cvta_generic_to_shared(sBl);
    // A: groups (m+l8,k0),(m+8+l8,k0),(m+l8,k8),(m+8+l8,k8)
    const uint32_t aoff = ((warp_m * 32 + (grp & 1) * 8 + l8) * AST + (grp >> 1) * 8) * 2;
    // B: groups (n+l8,k0),(n+l8,k8),(n+8+l8,k0),(n+8+l8,k8)
    const uint32_t boff = ((warp_n * 64 + (grp >> 1) * 8 + l8) * AST + (grp & 1) * 8) * 2;

    float acc[2][8][4];
#pragma unroll
    for (int mt = 0; mt < 2; mt++)
#pragma unroll
        for (int nt = 0; nt < 8; nt++)
#pragma unroll
            for (int i = 0; i < 4; i++) acc[mt][nt][i] = 0.0f;

    for (int kc = 0; kc < 512; kc += KC) {
        // gmem -> smem: 2 uint4 (16 bf16) per array per thread
        {
            const int ga = (m0 + lr) * 512 + kc + lc;
            *(uint4*)&sAh[lr * AST + lc]     = *(const uint4*)&Ah[ga];
            *(uint4*)&sAh[lr * AST + lc + 8] = *(const uint4*)&Ah[ga + 8];
            *(uint4*)&sAl[lr * AST + lc]     = *(const uint4*)&Al[ga];
            *(uint4*)&sAl[lr * AST + lc + 8] = *(const uint4*)&Al[ga + 8];
            const int gb = (n0 + lr) * 512 + kc + lc;
            *(uint4*)&sBh[lr * AST + lc]     = *(const uint4*)&Bh[gb];
            *(uint4*)&sBh[lr * AST + lc + 8] = *(const uint4*)&Bh[gb + 8];
            *(uint4*)&sBl[lr * AST + lc]     = *(const uint4*)&Bl[gb];
            *(uint4*)&sBl[lr * AST + lc + 8] = *(const uint4*)&Bl[gb + 8];
        }
        __syncthreads();

#pragma unroll
        for (int ks = 0; ks < KC; ks += 16) {
            uint32_t ah[2][4], al[2][4], bh[4][4], bl[4][4];
#pragma unroll
            for (int mt = 0; mt < 2; mt++) {
                ldsm_x4(ah[mt], sAh_b + aoff + mt * (16 * AST * 2) + ks * 2);
                ldsm_x4(al[mt], sAl_b + aoff + mt * (16 * AST * 2) + ks * 2);
            }
#pragma unroll
            for (int j = 0; j < 4; j++) {
                ldsm_x4(bh[j], sBh_b + boff + j * (16 * AST * 2) + ks * 2);
                ldsm_x4(bl[j], sBl_b + boff + j * (16 * AST * 2) + ks * 2);
            }
#pragma unroll
            for (int mt = 0; mt < 2; mt++)
#pragma unroll
                for (int nt = 0; nt < 8; nt++) {
                    const uint32_t* ph = &bh[nt >> 1][(nt & 1) * 2];
                    const uint32_t* pl = &bl[nt >> 1][(nt & 1) * 2];
                    mma_bf16(acc[mt][nt], ah[mt], ph);   // Ah*Bh
                    mma_bf16(acc[mt][nt], ah[mt], pl);   // Ah*Bl
                    mma_bf16(acc[mt][nt], al[mt], ph);   // Al*Bh
                }
        }
        __syncthreads();
    }

    // writeback: c0,c1=(g,2t),(g,2t+1); c2,c3=(g+8,2t),(g+8,2t+1)
    const int g = lane >> 2, t = lane & 3;
#pragma unroll
    for (int mt = 0; mt < 2; mt++) {
        const int row = m0 + warp_m * 32 + mt * 16 + g;
#pragma unroll
        for (int nt = 0; nt < 8; nt++) {
            const int col = n0 + warp_n * 64 + nt * 8 + t * 2;
            *(float2*)&C[row * 512 + col]       = make_float2(acc[mt][nt][0], acc[mt][nt][1]);
            *(float2*)&C[(row + 8) * 512 + col] = make_float2(acc[mt][nt][2], acc[mt][nt][3]);
        }
    }
}

// ----------------------------------------------------------------------------
// Kernel: partial scores (unchanged from R9). Task t: hh=t&1, b=(t>>1)&15, qt=t>>5.
// ----------------------------------------------------------------------------
#define HC 64
#define KS_STRIDE 68
#define POOL_FLOATS (128 * KS_STRIDE + 16 * KS_STRIDE + HDIM)

__global__ __launch_bounds__(512, 1) void score_kernel(
    const int* __restrict__ valid_lens,
    const float* __restrict__ wv)
{
    const int tid = threadIdx.x;
    const int tk  = tid & 31;
    const int w   = tid >> 5;

    __shared__ __align__(16) float pool[POOL_FLOATS];
    float (*Ks)[KS_STRIDE] = (float(*)[KS_STRIDE])&pool[0];
    float (*Qs)[KS_STRIDE] = (float(*)[KS_STRIDE])&pool[128 * KS_STRIDE];
    float* wvs = &pool[144 * KS_STRIDE];
    __shared__ int s_task;

    if (tid < 128)
        *(float4*)&wvs[tid * 4] = *(const float4*)&wv[tid * 4];

    const int kq_row = tid >> 4;
    const int kq_c4  = tid & 15;
    const int q_row  = tid >> 4;
    const int q_c4   = tid & 15;

    for (;;) {
        if (tid == 0) s_task = atomicAdd(&g_counter, 1);
        __syncthreads();
        const int t = s_task;
        if (t >= NTASKS) break;

        const int hh = t & 1;
        const int b  = (t >> 1) & 15;
        const int qt = t >> 5;
        const int vlen = valid_lens[b];
        const int kmax = min(KDIM, (vlen + 31) & ~31);
        const bool act1 = (32 < vlen);
        const bool act2 = (64 < vlen);
        const bool act3 = (96 < vlen);
        const int hbase = hh * (HDIM / 2);

        const float* Qp = g_Qp + (b * QDIM + qt * 16) * HDIM;
        const float* Kp = g_Kp + b * KDIM * HDIM;

        float4 pk[4];
        float4 pq;

#pragma unroll
        for (int i = 0; i < 4; i++)
            if (kq_row + 32 * i < kmax)
                pk[i] = *(const float4*)&Kp[(kq_row + 32 * i) * HDIM + hbase + kq_c4 * 4];
        if (tid < 256)
            pq = *(const float4*)&Qp[q_row * HDIM + hbase + q_c4 * 4];

#pragma unroll
        for (int i = 0; i < 4; i++)
            if (kq_row + 32 * i < kmax)
                *(float4*)&Ks[kq_row + 32 * i][kq_c4 * 4] = pk[i];
        if (tid < 256)
            *(float4*)&Qs[q_row][q_c4 * 4] = pq;
        __syncthreads();

        float s0 = 0.0f, s1 = 0.0f, s2 = 0.0f, s3 = 0.0f;

        const int NCH = (HDIM / 2) / HC;
        for (int hc = 0; hc < NCH; ++hc) {
            const int h0 = hbase + hc * HC;
            if (hc + 1 < NCH) {
                const int hn = h0 + HC;
#pragma unroll
                for (int i = 0; i < 4; i++)
                    if (kq_row + 32 * i < kmax)
                        pk[i] = *(const float4*)&Kp[(kq_row + 32 * i) * HDIM + hn + kq_c4 * 4];
                if (tid < 256)
                    pq = *(const float4*)&Qp[q_row * HDIM + hn + q_c4 * 4];
            }

#pragma unroll
            for (int h4 = 0; h4 < HC / 4; ++h4) {
                const float4 w4 = *(const float4*)&wvs[h0 + h4 * 4];
                const float4 qa = *(const float4*)&Qs[w][h4 * 4];
                {
                    const float4 kv = *(const float4*)&Ks[tk][h4 * 4];
                    s0 = fmaf(tanh_fast(qa.x + kv.x), w4.x, s0);
                    s0 = fmaf(tanh_fast(qa.y + kv.y), w4.y, s0);
                    s0 = fmaf(tanh_fast(qa.z + kv.z), w4.z, s0);
                    s0 = fmaf(tanh_fast(qa.w + kv.w), w4.w, s0);
                }
                if (act1) {
                    const float4 kv = *(const float4*)&Ks[tk + 32][h4 * 4];
                    s1 = fmaf(tanh_fast(qa.x + kv.x), w4.x, s1);
                    s1 = fmaf(tanh_fast(qa.y + kv.y), w4.y, s1);
                    s1 = fmaf(tanh_fast(qa.z + kv.z), w4.z, s1);
                    s1 = fmaf(tanh_fast(qa.w + kv.w), w4.w, s1);
                }
                if (act2) {
                    const float4 kv = *(const float4*)&Ks[tk + 64][h4 * 4];
                    s2 = fmaf(tanh_fast(qa.x + kv.x), w4.x, s2);
                    s2 = fmaf(tanh_fast(qa.y + kv.y), w4.y, s2);
                    s2 = fmaf(tanh_fast(qa.z + kv.z), w4.z, s2);
                    s2 = fmaf(tanh_fast(qa.w + kv.w), w4.w, s2);
                }
                if (act3) {
                    const float4 kv = *(const float4*)&Ks[tk + 96][h4 * 4];
                    s3 = fmaf(tanh_fast(qa.x + kv.x), w4.x, s3);
                    s3 = fmaf(tanh_fast(qa.y + kv.y), w4.y, s3);
                    s3 = fmaf(tanh_fast(qa.z + kv.z), w4.z, s3);
                    s3 = fmaf(tanh_fast(qa.w + kv.w), w4.w, s3);
                }
            }
            __syncthreads();
            if (hc + 1 < NCH) {
#pragma unroll
                for (int i = 0; i < 4; i++)
                    if (kq_row + 32 * i < kmax)
                        *(float4*)&Ks[kq_row + 32 * i][kq_c4 * 4] = pk[i];
                if (tid < 256)
                    *(float4*)&Qs[q_row][q_c4 * 4] = pq;
                __syncthreads();
            }
        }

        float* Sp = &g_S[hh][b][qt * 16 + w][0];
        Sp[tk] = s0;
        if (act1) Sp[tk + 32] = s1;
        if (act2) Sp[tk + 64] = s2;
        if (act3) Sp[tk + 96] = s3;
    }

    if (tid == 0) {
        __threadfence();
        const int d = atomicAdd(&g_done, 1);
        if (d == NBLOCKS - 1) { g_counter = 0; g_done = 0; }
    }
}

// ----------------------------------------------------------------------------
// Kernel: sum partials, masked softmax, attn@V (unchanged from R9).
// ----------------------------------------------------------------------------
__global__ __launch_bounds__(512, 1) void softmax_av(
    const float* __restrict__ values,
    const int* __restrict__ valid_lens,
    float* __restrict__ out)
{
    const int b  = blockIdx.y;
    const int qt = blockIdx.x;
    const int tid = threadIdx.x;
    const int tk  = tid & 31;
    const int w   = tid >> 5;

    __shared__ __align__(16) float attnT[128][20];

    const int vlen = valid_lens[b];
    const int kmax = min(KDIM, (vlen + 31) & ~31);

    const float* S0 = &g_S[0][b][qt * 16 + w][0];
    const float* S1 = &g_S[1][b][qt * 16 + w][0];

    float s[4];
#pragma unroll
    for (int j = 0; j < 4; j++) {
        const int k = tk + 32 * j;
        s[j] = (k < kmax) ? (S0[k] + S1[k]) : -1e6f;
        if (k >= vlen) s[j] = -1e6f;
    }

    float m = fmaxf(fmaxf(s[0], s[1]), fmaxf(s[2], s[3]));
#pragma unroll
    for (int off = 16; off > 0; off >>= 1)
        m = fmaxf(m, __shfl_xor_sync(0xFFFFFFFFu, m, off));
    float sum = 0.0f;
#pragma unroll
    for (int j = 0; j < 4; j++) {
        s[j] = __expf(s[j] - m);
        sum += s[j];
    }
#pragma unroll
    for (int off = 16; off > 0; off >>= 1)
        sum += __shfl_xor_sync(0xFFFFFFFFu, sum, off);
    const float rs = 1.0f / sum;
#pragma unroll
    for (int j = 0; j < 4; j++)
        attnT[tk + 32 * j][w] = s[j] * rs;
    __syncthreads();

    const int d = tid;
    const float* Vb = values + b * KDIM * DDIM + d;
    float acc[16];
#pragma unroll
    for (int q = 0; q < 16; q++) acc[q] = 0.0f;

    for (int k = 0; k < kmax; ++k) {
        const float v = Vb[k * DDIM];
        float a[16];
        *(float4*)&a[0]  = *(const float4*)&attnT[k][0];
        *(float4*)&a[4]  = *(const float4*)&attnT[k][4];
        *(float4*)&a[8]  = *(const float4*)&attnT[k][8];
        *(float4*)&a[12] = *(const float4*)&attnT[k][12];
#pragma unroll
        for (int q = 0; q < 16; q++)
            acc[q] = fmaf(a[q], v, acc[q]);
    }

    float* Ob = out + (b * QDIM + qt * 16) * DDIM + d;
#pragma unroll
    for (int q = 0; q < 16; q++)
        Ob[q * DDIM] = acc[q];
}

// ----------------------------------------------------------------------------
extern "C" void kernel_launch(void* const* d_in, const int* in_sizes, int n_in,
                              void* d_out, int out_size)
{
    const float* queries    = (const float*)d_in[0];
    const float* keys       = (const float*)d_in[1];
    const float* values     = (const float*)d_in[2];
    const int*   valid_lens = (const int*)d_in[3];
    const float* Wq         = (const float*)d_in[4];
    const float* Wk         = (const float*)d_in[5];
    const float* wv         = (const float*)d_in[6];
    float* out = (float*)d_out;

    prep_a<<<dim3(1024, 2), 256>>>(queries, keys);
    prep_w<<<dim3(16, 16, 2), dim3(32, 32)>>>(Wq, Wk);
    bf16_gemm<<<dim3(4, 16, 2), 256>>>();
    score_kernel<<<NBLOCKS, 512>>>(valid_lens, wv);
    softmax_av<<<dim3(8, 16), 512>>>(values, valid_lens, out);
}

// round 12
// speedup vs baseline: 1.2876x; 1.1067x over previous
#include <cuda_runtime.h>
#include <cuda_bf16.h>
#include <cstdint>

// ============================================================================
// AdditiveAttention: out = softmax_mask( sum_h tanh(Q@Wq + K@Wk) * wv ) @ V
// B=16, Q=128, K=128, D=512, H=512
//  prep_a / prep_w : fp32 -> bf16 (hi, lo) split copies; W also transposed
//  bf16_gemm      : Qp/Kp = A@W via mma.sync m16n8k16 bf16, 3-term split
//  score_kernel   : persistent 296 x 512thr (2 blocks/SM via 23.8KB smem),
//                   512 tasks (b, 16 q-rows, h-half, k-half); empty-task skip
//  softmax_av     : sum halves, masked softmax, AV
// ============================================================================

#define BDIM 16
#define QDIM 128
#define KDIM 128
#define DDIM 512
#define HDIM 512
#define NTASKS 512
#define NBLOCKS 296

__device__ float g_Qp[BDIM * QDIM * HDIM];     // 4 MB
__device__ float g_Kp[BDIM * KDIM * HDIM];     // 4 MB
__device__ float g_S[2][BDIM][QDIM][KDIM];     // partial scores, 2 MB
__device__ int   g_counter;
__device__ int   g_done;

// bf16-split operands (ushort = raw bf16 bits)
__device__ unsigned short g_Ah[2][2048 * 512];
__device__ unsigned short g_Al[2][2048 * 512];
__device__ unsigned short g_Bth[2][512 * 512];   // W^T : [n][k]
__device__ unsigned short g_Btl[2][512 * 512];

__device__ __forceinline__ float tanh_fast(float x) {
    float y;
    asm("tanh.approx.f32 %0, %1;" : "=f"(y) : "f"(x));
    return y;
}
__device__ __forceinline__ void bf16_split(float x, unsigned short& hi, unsigned short& lo) {
    __nv_bfloat16 h = __float2bfloat16_rn(x);
    __nv_bfloat16 l = __float2bfloat16_rn(x - __bfloat162float(h));
    hi = __bfloat16_as_ushort(h);
    lo = __bfloat16_as_ushort(l);
}
__device__ __forceinline__ void ldsm_x4(uint32_t* r, uint32_t addr) {
    asm volatile("ldmatrix.sync.aligned.m8n8.x4.shared.b16 {%0,%1,%2,%3}, [%4];"
        : "=r"(r[0]), "=r"(r[1]), "=r"(r[2]), "=r"(r[3]) : "r"(addr));
}
__device__ __forceinline__ void mma_bf16(float* c, const uint32_t* a, const uint32_t* b) {
    asm volatile("mma.sync.aligned.m16n8k16.row.col.f32.bf16.bf16.f32 "
        "{%0,%1,%2,%3}, {%4,%5,%6,%7}, {%8,%9}, {%0,%1,%2,%3};"
        : "+f"(c[0]), "+f"(c[1]), "+f"(c[2]), "+f"(c[3])
        : "r"(a[0]), "r"(a[1]), "r"(a[2]), "r"(a[3]), "r"(b[0]), "r"(b[1]));
}

// ----------------------------------------------------------------------------
__global__ void prep_a(const float* __restrict__ Aq, const float* __restrict__ Ak)
{
    const int z = blockIdx.y;
    const float* A = z ? Ak : Aq;
    const int idx = blockIdx.x * 256 + threadIdx.x;
    const float4 v = ((const float4*)A)[idx];
    ushort4 h, l;
    bf16_split(v.x, h.x, l.x);
    bf16_split(v.y, h.y, l.y);
    bf16_split(v.z, h.z, l.z);
    bf16_split(v.w, h.w, l.w);
    ((ushort4*)g_Ah[z])[idx] = h;
    ((ushort4*)g_Al[z])[idx] = l;
}

__global__ void prep_w(const float* __restrict__ Wq, const float* __restrict__ Wk)
{
    __shared__ float tile[32][33];
    const int z = blockIdx.z;
    const float* W = z ? Wk : Wq;
    const int k = blockIdx.y * 32 + threadIdx.y;
    const int n = blockIdx.x * 32 + threadIdx.x;
    tile[threadIdx.y][threadIdx.x] = W[k * 512 + n];
    __syncthreads();
    const int on = blockIdx.x * 32 + threadIdx.y;
    const int ok = blockIdx.y * 32 + threadIdx.x;
    unsigned short hi, lo;
    bf16_split(tile[threadIdx.x][threadIdx.y], hi, lo);
    g_Bth[z][on * 512 + ok] = hi;
    g_Btl[z][on * 512 + ok] = lo;
}

// ----------------------------------------------------------------------------
// bf16_gemm: C[2048,512] = A@W per z. 128x128 tile, KC=32, 256 thr (8 warps
// as 4x2), warp tile 32x64. 3-term split: AhBh + AhBl + AlBh.
// ----------------------------------------------------------------------------
#define KC 32
#define AST 40

__global__ __launch_bounds__(256, 1) void bf16_gemm()
{
    const int z  = blockIdx.z;
    const int m0 = blockIdx.y * 128;
    const int n0 = blockIdx.x * 128;

    const unsigned short* Ah = g_Ah[z];
    const unsigned short* Al = g_Al[z];
    const unsigned short* Bh = g_Bth[z];
    const unsigned short* Bl = g_Btl[z];
    float* C = z ? g_Kp : g_Qp;

    __shared__ __align__(16) unsigned short sAh[128 * AST];
    __shared__ __align__(16) unsigned short sAl[128 * AST];
    __shared__ __align__(16) unsigned short sBh[128 * AST];
    __shared__ __align__(16) unsigned short sBl[128 * AST];

    const int tid  = threadIdx.x;
    const int lane = tid & 31;
    const int wid  = tid >> 5;
    const int warp_m = wid & 3;
    const int warp_n = wid >> 2;

    const int lr = tid >> 1;
    const int lc = (tid & 1) * 16;

    const int grp = lane >> 3, l8 = lane & 7;
    const uint32_t sAh_b = (uint32_t)__cvta_generic_to_shared(sAh);
    const uint32_t sAl_b = (uint32_t)__cvta_generic_to_shared(sAl);
    const uint32_t sBh_b = (uint32_t)__cvta_generic_to_shared(sBh);
    const uint32_t sBl_b = (uint32_t)__cvta_generic_to_shared(sBl);
    const uint32_t aoff = ((warp_m * 32 + (grp & 1) * 8 + l8) * AST + (grp >> 1) * 8) * 2;
    const uint32_t boff = ((warp_n * 64 + (grp >> 1) * 8 + l8) * AST + (grp & 1) * 8) * 2;

    float acc[2][8][4];
#pragma unroll
    for (int mt = 0; mt < 2; mt++)
#pragma unroll
        for (int nt = 0; nt < 8; nt++)
#pragma unroll
            for (int i = 0; i < 4; i++) acc[mt][nt][i] = 0.0f;

    for (int kc = 0; kc < 512; kc += KC) {
        {
            const int ga = (m0 + lr) * 512 + kc + lc;
            *(uint4*)&sAh[lr * AST + lc]     = *(const uint4*)&Ah[ga];
            *(uint4*)&sAh[lr * AST + lc + 8] = *(const uint4*)&Ah[ga + 8];
            *(uint4*)&sAl[lr * AST + lc]     = *(const uint4*)&Al[ga];
            *(uint4*)&sAl[lr * AST + lc + 8] = *(const uint4*)&Al[ga + 8];
            const int gb = (n0 + lr) * 512 + kc + lc;
            *(uint4*)&sBh[lr * AST + lc]     = *(const uint4*)&Bh[gb];
            *(uint4*)&sBh[lr * AST + lc + 8] = *(const uint4*)&Bh[gb + 8];
            *(uint4*)&sBl[lr * AST + lc]     = *(const uint4*)&Bl[gb];
            *(uint4*)&sBl[lr * AST + lc + 8] = *(const uint4*)&Bl[gb + 8];
        }
        __syncthreads();

#pragma unroll
        for (int ks = 0; ks < KC; ks += 16) {
            uint32_t ah[2][4], al[2][4], bh[4][4], bl[4][4];
#pragma unroll
            for (int mt = 0; mt < 2; mt++) {
                ldsm_x4(ah[mt], sAh_b + aoff + mt * (16 * AST * 2) + ks * 2);
                ldsm_x4(al[mt], sAl_b + aoff + mt * (16 * AST * 2) + ks * 2);
            }
#pragma unroll
            for (int j = 0; j < 4; j++) {
                ldsm_x4(bh[j], sBh_b + boff + j * (16 * AST * 2) + ks * 2);
                ldsm_x4(bl[j], sBl_b + boff + j * (16 * AST * 2) + ks * 2);
            }
#pragma unroll
            for (int mt = 0; mt < 2; mt++)
#pragma unroll
                for (int nt = 0; nt < 8; nt++) {
                    const uint32_t* ph = &bh[nt >> 1][(nt & 1) * 2];
                    const uint32_t* pl = &bl[nt >> 1][(nt & 1) * 2];
                    mma_bf16(acc[mt][nt], ah[mt], ph);
                    mma_bf16(acc[mt][nt], ah[mt], pl);
                    mma_bf16(acc[mt][nt], al[mt], ph);
                }
        }
        __syncthreads();
    }

    const int g = lane >> 2, t = lane & 3;
#pragma unroll
    for (int mt = 0; mt < 2; mt++) {
        const int row = m0 + warp_m * 32 + mt * 16 + g;
#pragma unroll
        for (int nt = 0; nt < 8; nt++) {
            const int col = n0 + warp_n * 64 + nt * 8 + t * 2;
            *(float2*)&C[row * 512 + col]       = make_float2(acc[mt][nt][0], acc[mt][nt][1]);
            *(float2*)&C[(row + 8) * 512 + col] = make_float2(acc[mt][nt][2], acc[mt][nt][3]);
        }
    }
}

// ----------------------------------------------------------------------------
// score_kernel: partial scores, k-split for 2-blocks/SM occupancy.
// Task t: kh = t&1, hh = (t>>1)&1, b = (t>>2)&15, qt = t>>6.
// Writes S[hh][b][qt*16+w][kh*64 + {tk, tk+32}]. Tasks with kh*64 >= kmax
// exit immediately. Ks holds 64 k-rows; h-half = 4 chunks of 64, reg dbuf.
// ----------------------------------------------------------------------------
#define HC 64
#define KS_STRIDE 68
#define POOL_FLOATS (64 * KS_STRIDE + 16 * KS_STRIDE + HDIM)   // 5952 = 23.8KB

__global__ __launch_bounds__(512, 2) void score_kernel(
    const int* __restrict__ valid_lens,
    const float* __restrict__ wv)
{
    const int tid = threadIdx.x;
    const int tk  = tid & 31;
    const int w   = tid >> 5;         // 0..15 -> q-row within tile

    __shared__ __align__(16) float pool[POOL_FLOATS];
    float (*Ks)[KS_STRIDE] = (float(*)[KS_STRIDE])&pool[0];                // 64x68
    float (*Qs)[KS_STRIDE] = (float(*)[KS_STRIDE])&pool[64 * KS_STRIDE];   // 16x68
    float* wvs = &pool[80 * KS_STRIDE];                                    // 512
    __shared__ int s_task;

    if (tid < 128)
        *(float4*)&wvs[tid * 4] = *(const float4*)&wv[tid * 4];

    // Ks chunk = 64 rows x 16 float4 = 1024 float4 / 512 thr -> 2 each
    const int kq_row = tid >> 4;      // 0..31 (+32)
    const int kq_c4  = tid & 15;
    const int q_row  = tid >> 4;      // 0..15 for tid<256
    const int q_c4   = tid & 15;

    for (;;) {
        if (tid == 0) s_task = atomicAdd(&g_counter, 1);
        __syncthreads();
        const int t = s_task;
        if (t >= NTASKS) break;

        const int kh = t & 1;
        const int hh = (t >> 1) & 1;
        const int b  = (t >> 2) & 15;
        const int qt = t >> 6;                 // 0..7
        const int vlen = valid_lens[b];
        const int kmax = min(KDIM, (vlen + 31) & ~31);
        const int kbase = kh * 64;

        if (kbase >= kmax) { __syncthreads(); continue; }   // empty task

        const bool act1 = (kbase + 32 < vlen);
        const int hbase = hh * (HDIM / 2);     // 0 or 256

        const float* Qp = g_Qp + (b * QDIM + qt * 16) * HDIM;
        const float* Kp = g_Kp + (b * KDIM + kbase) * HDIM;

        float4 pk[2];
        float4 pq;

        // prefetch chunk 0 (rows bounded by kmax-kbase)
        const int krows = kmax - kbase;        // 32 or 64 (per this task)
#pragma unroll
        for (int i = 0; i < 2; i++)
            if (kq_row + 32 * i < krows)
                pk[i] = *(const float4*)&Kp[(kq_row + 32 * i) * HDIM + hbase + kq_c4 * 4];
        if (tid < 256)
            pq = *(const float4*)&Qp[q_row * HDIM + hbase + q_c4 * 4];

#pragma unroll
        for (int i = 0; i < 2; i++)
            if (kq_row + 32 * i < krows)
                *(float4*)&Ks[kq_row + 32 * i][kq_c4 * 4] = pk[i];
        if (tid < 256)
            *(float4*)&Qs[q_row][q_c4 * 4] = pq;
        __syncthreads();

        float s0 = 0.0f, s1 = 0.0f;

        const int NCH = (HDIM / 2) / HC;   // 4
        for (int hc = 0; hc < NCH; ++hc) {
            const int h0 = hbase + hc * HC;
            if (hc + 1 < NCH) {
                const int hn = h0 + HC;
#pragma unroll
                for (int i = 0; i < 2; i++)
                    if (kq_row + 32 * i < krows)
                        pk[i] = *(const float4*)&Kp[(kq_row + 32 * i) * HDIM + hn + kq_c4 * 4];
                if (tid < 256)
                    pq = *(const float4*)&Qp[q_row * HDIM + hn + q_c4 * 4];
            }

#pragma unroll
            for (int h4 = 0; h4 < HC / 4; ++h4) {
                const float4 w4 = *(const float4*)&wvs[h0 + h4 * 4];
                const float4 qa = *(const float4*)&Qs[w][h4 * 4];
                {
                    const float4 kv = *(const float4*)&Ks[tk][h4 * 4];
                    s0 = fmaf(tanh_fast(qa.x + kv.x), w4.x, s0);
                    s0 = fmaf(tanh_fast(qa.y + kv.y), w4.y, s0);
                    s0 = fmaf(tanh_fast(qa.z + kv.z), w4.z, s0);
                    s0 = fmaf(tanh_fast(qa.w + kv.w), w4.w, s0);
                }
                if (act1) {
                    const float4 kv = *(const float4*)&Ks[tk + 32][h4 * 4];
                    s1 = fmaf(tanh_fast(qa.x + kv.x), w4.x, s1);
                    s1 = fmaf(tanh_fast(qa.y + kv.y), w4.y, s1);
                    s1 = fmaf(tanh_fast(qa.z + kv.z), w4.z, s1);
                    s1 = fmaf(tanh_fast(qa.w + kv.w), w4.w, s1);
                }
            }
            __syncthreads();
            if (hc + 1 < NCH) {
#pragma unroll
                for (int i = 0; i < 2; i++)
                    if (kq_row + 32 * i < krows)
                        *(float4*)&Ks[kq_row + 32 * i][kq_c4 * 4] = pk[i];
                if (tid < 256)
                    *(float4*)&Qs[q_row][q_c4 * 4] = pq;
                __syncthreads();
            }
        }

        float* Sp = &g_S[hh][b][qt * 16 + w][0];
        Sp[kbase + tk] = s0;
        if (act1) Sp[kbase + tk + 32] = s1;
    }

    if (tid == 0) {
        __threadfence();
        const int d = atomicAdd(&g_done, 1);
        if (d == NBLOCKS - 1) { g_counter = 0; g_done = 0; }
    }
}

// ----------------------------------------------------------------------------
// softmax_av: sum partials, masked softmax, attn@V (unchanged).
// ----------------------------------------------------------------------------
__global__ __launch_bounds__(512, 1) void softmax_av(
    const float* __restrict__ values,
    const int* __restrict__ valid_lens,
    float* __restrict__ out)
{
    const int b  = blockIdx.y;
    const int qt = blockIdx.x;
    const int tid = threadIdx.x;
    const int tk  = tid & 31;
    const int w   = tid >> 5;

    __shared__ __align__(16) float attnT[128][20];

    const int vlen = valid_lens[b];
    const int kmax = min(KDIM, (vlen + 31) & ~31);

    const float* S0 = &g_S[0][b][qt * 16 + w][0];
    const float* S1 = &g_S[1][b][qt * 16 + w][0];

    float s[4];
#pragma unroll
    for (int j = 0; j < 4; j++) {
        const int k = tk + 32 * j;
        s[j] = (k < kmax) ? (S0[k] + S1[k]) : -1e6f;
        if (k >= vlen) s[j] = -1e6f;
    }

    float m = fmaxf(fmaxf(s[0], s[1]), fmaxf(s[2], s[3]));
#pragma unroll
    for (int off = 16; off > 0; off >>= 1)
        m = fmaxf(m, __shfl_xor_sync(0xFFFFFFFFu, m, off));
    float sum = 0.0f;
#pragma unroll
    for (int j = 0; j < 4; j++) {
        s[j] = __expf(s[j] - m);
        sum += s[j];
    }
#pragma unroll
    for (int off = 16; off > 0; off >>= 1)
        sum += __shfl_xor_sync(0xFFFFFFFFu, sum, off);
    const float rs = 1.0f / sum;
#pragma unroll
    for (int j = 0; j < 4; j++)
        attnT[tk + 32 * j][w] = s[j] * rs;
    __syncthreads();

    const int d = tid;
    const float* Vb = values + b * KDIM * DDIM + d;
    float acc[16];
#pragma unroll
    for (int q = 0; q < 16; q++) acc[q] = 0.0f;

    for (int k = 0; k < kmax; ++k) {
        const float v = Vb[k * DDIM];
        float a[16];
        *(float4*)&a[0]  = *(const float4*)&attnT[k][0];
        *(float4*)&a[4]  = *(const float4*)&attnT[k][4];
        *(float4*)&a[8]  = *(const float4*)&attnT[k][8];
        *(float4*)&a[12] = *(const float4*)&attnT[k][12];
#pragma unroll
        for (int q = 0; q < 16; q++)
            acc[q] = fmaf(a[q], v, acc[q]);
    }

    float* Ob = out + (b * QDIM + qt * 16) * DDIM + d;
#pragma unroll
    for (int q = 0; q < 16; q++)
        Ob[q * DDIM] = acc[q];
}

// ----------------------------------------------------------------------------
extern "C" void kernel_launch(void* const* d_in, const int* in_sizes, int n_in,
                              void* d_out, int out_size)
{
    const float* queries    = (const float*)d_in[0];
    const float* keys       = (const float*)d_in[1];
    const float* values     = (const float*)d_in[2];
    const int*   valid_lens = (const int*)d_in[3];
    const float* Wq         = (const float*)d_in[4];
    const float* Wk         = (const float*)d_in[5];
    const float* wv         = (const float*)d_in[6];
    float* out = (float*)d_out;

    prep_a<<<dim3(1024, 2), 256>>>(queries, keys);
    prep_w<<<dim3(16, 16, 2), dim3(32, 32)>>>(Wq, Wk);
    bf16_gemm<<<dim3(4, 16, 2), 256>>>();
    score_kernel<<<NBLOCKS, 512>>>(valid_lens, wv);
    softmax_av<<<dim3(8, 16), 512>>>(values, valid_lens, out);
}

// round 13
// speedup vs baseline: 1.4686x; 1.1406x over previous
#include <cuda_runtime.h>
#include <cuda_bf16.h>
#include <cstdint>

// ============================================================================
// AdditiveAttention: out = softmax_mask( sum_h tanh(Q@Wq + K@Wk) * wv ) @ V
// B=16, Q=128, K=128, D=512, H=512
//  prep          : fused fp32->bf16 hi/lo split of A (row-major) and W^T
//  bf16_gemm     : Qp/Kp = A@W via mma.sync m16n8k16 bf16, 3-term split,
//                  register-prefetch double-buffered k-chunks
//  score_kernel  : persistent 296 x 512thr (2 blocks/SM), 512 tasks
//                  (b, 16 q-rows, h-half, k-half); empty-task skip
//  softmax_av    : sum halves, masked softmax, AV
// ============================================================================

#define BDIM 16
#define QDIM 128
#define KDIM 128
#define DDIM 512
#define HDIM 512
#define NTASKS 512
#define NBLOCKS 296

__device__ float g_Qp[BDIM * QDIM * HDIM];     // 4 MB
__device__ float g_Kp[BDIM * KDIM * HDIM];     // 4 MB
__device__ float g_S[2][BDIM][QDIM][KDIM];     // partial scores, 2 MB
__device__ int   g_counter;
__device__ int   g_done;

__device__ unsigned short g_Ah[2][2048 * 512];
__device__ unsigned short g_Al[2][2048 * 512];
__device__ unsigned short g_Bth[2][512 * 512];   // W^T : [n][k]
__device__ unsigned short g_Btl[2][512 * 512];

__device__ __forceinline__ float tanh_fast(float x) {
    float y;
    asm("tanh.approx.f32 %0, %1;" : "=f"(y) : "f"(x));
    return y;
}
__device__ __forceinline__ void bf16_split(float x, unsigned short& hi, unsigned short& lo) {
    __nv_bfloat16 h = __float2bfloat16_rn(x);
    __nv_bfloat16 l = __float2bfloat16_rn(x - __bfloat162float(h));
    hi = __bfloat16_as_ushort(h);
    lo = __bfloat16_as_ushort(l);
}
__device__ __forceinline__ void ldsm_x4(uint32_t* r, uint32_t addr) {
    asm volatile("ldmatrix.sync.aligned.m8n8.x4.shared.b16 {%0,%1,%2,%3}, [%4];"
        : "=r"(r[0]), "=r"(r[1]), "=r"(r[2]), "=r"(r[3]) : "r"(addr));
}
__device__ __forceinline__ void mma_bf16(float* c, const uint32_t* a, const uint32_t* b) {
    asm volatile("mma.sync.aligned.m16n8k16.row.col.f32.bf16.bf16.f32 "
        "{%0,%1,%2,%3}, {%4,%5,%6,%7}, {%8,%9}, {%0,%1,%2,%3};"
        : "+f"(c[0]), "+f"(c[1]), "+f"(c[2]), "+f"(c[3])
        : "r"(a[0]), "r"(a[1]), "r"(a[2]), "r"(a[3]), "r"(b[0]), "r"(b[1]));
}

// ----------------------------------------------------------------------------
// prep: fused. grid (1280, 2) x 256 threads.
//   x <  1024 : A split — one float4 per thread, row-major hi/lo
//   x >= 1024 : W^T split — 32x32 tile transpose (block = one tile)
// ----------------------------------------------------------------------------
__global__ void prep(const float* __restrict__ Aq, const float* __restrict__ Ak,
                     const float* __restrict__ Wq, const float* __restrict__ Wk)
{
    __shared__ float tile[32][33];
    const int z = blockIdx.y;
    const int bx = blockIdx.x;
    const int tid = threadIdx.x;

    if (bx < 1024) {
        const float* A = z ? Ak : Aq;
        const int idx = bx * 256 + tid;
        const float4 v = ((const float4*)A)[idx];
        ushort4 h, l;
        bf16_split(v.x, h.x, l.x);
        bf16_split(v.y, h.y, l.y);
        bf16_split(v.z, h.z, l.z);
        bf16_split(v.w, h.w, l.w);
        ((ushort4*)g_Ah[z])[idx] = h;
        ((ushort4*)g_Al[z])[idx] = l;
    } else {
        const float* W = z ? Wk : Wq;
        const int wb = bx - 1024;          // 0..255
        const int n0 = (wb & 15) * 32;
        const int k0 = (wb >> 4) * 32;
        const int tx = tid & 31;
        const int ty = tid >> 5;           // 0..7
#pragma unroll
        for (int i = 0; i < 4; i++) {
            const int r = ty + i * 8;      // k-local
            tile[r][tx] = W[(k0 + r) * 512 + n0 + tx];
        }
        __syncthreads();
#pragma unroll
        for (int i = 0; i < 4; i++) {
            const int r = ty + i * 8;      // n-local
            unsigned short hi, lo;
            bf16_split(tile[tx][r], hi, lo);
            g_Bth[z][(n0 + r) * 512 + k0 + tx] = hi;
            g_Btl[z][(n0 + r) * 512 + k0 + tx] = lo;
        }
    }
}

// ----------------------------------------------------------------------------
// bf16_gemm: C[2048,512] = A@W per z. 128x128 tile, KC=32, 256 thr (8 warps
// as 4x2), warp tile 32x64. 3-term split: AhBh + AhBl + AlBh.
// Register-prefetch double-buffered k-chunks.
// ----------------------------------------------------------------------------
#define KC 32
#define AST 40

__global__ __launch_bounds__(256, 1) void bf16_gemm()
{
    const int z  = blockIdx.z;
    const int m0 = blockIdx.y * 128;
    const int n0 = blockIdx.x * 128;

    const unsigned short* Ah = g_Ah[z];
    const unsigned short* Al = g_Al[z];
    const unsigned short* Bh = g_Bth[z];
    const unsigned short* Bl = g_Btl[z];
    float* C = z ? g_Kp : g_Qp;

    __shared__ __align__(16) unsigned short sAh[128 * AST];
    __shared__ __align__(16) unsigned short sAl[128 * AST];
    __shared__ __align__(16) unsigned short sBh[128 * AST];
    __shared__ __align__(16) unsigned short sBl[128 * AST];

    const int tid  = threadIdx.x;
    const int lane = tid & 31;
    const int wid  = tid >> 5;
    const int warp_m = wid & 3;
    const int warp_n = wid >> 2;

    const int lr = tid >> 1;
    const int lc = (tid & 1) * 16;

    const int grp = lane >> 3, l8 = lane & 7;
    const uint32_t sAh_b = (uint32_t)__cvta_generic_to_shared(sAh);
    const uint32_t sAl_b = (uint32_t)__cvta_generic_to_shared(sAl);
    const uint32_t sBh_b = (uint32_t)__cvta_generic_to_shared(sBh);
    const uint32_t sBl_b = (uint32_t)__cvta_generic_to_shared(sBl);
    const uint32_t aoff = ((warp_m * 32 + (grp & 1) * 8 + l8) * AST + (grp >> 1) * 8) * 2;
    const uint32_t boff = ((warp_n * 64 + (grp >> 1) * 8 + l8) * AST + (grp & 1) * 8) * 2;

    float acc[2][8][4];
#pragma unroll
    for (int mt = 0; mt < 2; mt++)
#pragma unroll
        for (int nt = 0; nt < 8; nt++)
#pragma unroll
            for (int i = 0; i < 4; i++) acc[mt][nt][i] = 0.0f;

    const int ga0 = (m0 + lr) * 512 + lc;
    const int gb0 = (n0 + lr) * 512 + lc;

    // prefetch chunk 0 into registers
    uint4 rah0, rah1, ral0, ral1, rbh0, rbh1, rbl0, rbl1;
    rah0 = *(const uint4*)&Ah[ga0];     rah1 = *(const uint4*)&Ah[ga0 + 8];
    ral0 = *(const uint4*)&Al[ga0];     ral1 = *(const uint4*)&Al[ga0 + 8];
    rbh0 = *(const uint4*)&Bh[gb0];     rbh1 = *(const uint4*)&Bh[gb0 + 8];
    rbl0 = *(const uint4*)&Bl[gb0];     rbl1 = *(const uint4*)&Bl[gb0 + 8];

    const int NKC = 512 / KC;   // 16
    for (int it = 0; it < NKC; ++it) {
        // store current chunk regs -> smem
        *(uint4*)&sAh[lr * AST + lc]     = rah0;
        *(uint4*)&sAh[lr * AST + lc + 8] = rah1;
        *(uint4*)&sAl[lr * AST + lc]     = ral0;
        *(uint4*)&sAl[lr * AST + lc + 8] = ral1;
        *(uint4*)&sBh[lr * AST + lc]     = rbh0;
        *(uint4*)&sBh[lr * AST + lc + 8] = rbh1;
        *(uint4*)&sBl[lr * AST + lc]     = rbl0;
        *(uint4*)&sBl[lr * AST + lc + 8] = rbl1;
        __syncthreads();

        // issue next chunk loads (latency overlapped with MMA below)
        if (it + 1 < NKC) {
            const int ga = ga0 + (it + 1) * KC;
            const int gb = gb0 + (it + 1) * KC;
            rah0 = *(const uint4*)&Ah[ga];     rah1 = *(const uint4*)&Ah[ga + 8];
            ral0 = *(const uint4*)&Al[ga];     ral1 = *(const uint4*)&Al[ga + 8];
            rbh0 = *(const uint4*)&Bh[gb];     rbh1 = *(const uint4*)&Bh[gb + 8];
            rbl0 = *(const uint4*)&Bl[gb];     rbl1 = *(const uint4*)&Bl[gb + 8];
        }

#pragma unroll
        for (int ks = 0; ks < KC; ks += 16) {
            uint32_t ah[2][4], al[2][4], bh[4][4], bl[4][4];
#pragma unroll
            for (int mt = 0; mt < 2; mt++) {
                ldsm_x4(ah[mt], sAh_b + aoff + mt * (16 * AST * 2) + ks * 2);
                ldsm_x4(al[mt], sAl_b + aoff + mt * (16 * AST * 2) + ks * 2);
            }
#pragma unroll
            for (int j = 0; j < 4; j++) {
                ldsm_x4(bh[j], sBh_b + boff + j * (16 * AST * 2) + ks * 2);
                ldsm_x4(bl[j], sBl_b + boff + j * (16 * AST * 2) + ks * 2);
            }
#pragma unroll
            for (int mt = 0; mt < 2; mt++)
#pragma unroll
                for (int nt = 0; nt < 8; nt++) {
                    const uint32_t* ph = &bh[nt >> 1][(nt & 1) * 2];
                    const uint32_t* pl = &bl[nt >> 1][(nt & 1) * 2];
                    mma_bf16(acc[mt][nt], ah[mt], ph);
                    mma_bf16(acc[mt][nt], ah[mt], pl);
                    mma_bf16(acc[mt][nt], al[mt], ph);
                }
        }
        __syncthreads();
    }

    const int g = lane >> 2, t = lane & 3;
#pragma unroll
    for (int mt = 0; mt < 2; mt++) {
        const int row = m0 + warp_m * 32 + mt * 16 + g;
#pragma unroll
        for (int nt = 0; nt < 8; nt++) {
            const int col = n0 + warp_n * 64 + nt * 8 + t * 2;
            *(float2*)&C[row * 512 + col]       = make_float2(acc[mt][nt][0], acc[mt][nt][1]);
            *(float2*)&C[(row + 8) * 512 + col] = make_float2(acc[mt][nt][2], acc[mt][nt][3]);
        }
    }
}

// ----------------------------------------------------------------------------
// score_kernel: partial scores, k-split for 2-blocks/SM occupancy (unchanged).
// Task t: kh = t&1, hh = (t>>1)&1, b = (t>>2)&15, qt = t>>6.
// ----------------------------------------------------------------------------
#define HC 64
#define KS_STRIDE 68
#define POOL_FLOATS (64 * KS_STRIDE + 16 * KS_STRIDE + HDIM)   // 23.8KB

__global__ __launch_bounds__(512, 2) void score_kernel(
    const int* __restrict__ valid_lens,
    const float* __restrict__ wv)
{
    const int tid = threadIdx.x;
    const int tk  = tid & 31;
    const int w   = tid >> 5;

    __shared__ __align__(16) float pool[POOL_FLOATS];
    float (*Ks)[KS_STRIDE] = (float(*)[KS_STRIDE])&pool[0];
    float (*Qs)[KS_STRIDE] = (float(*)[KS_STRIDE])&pool[64 * KS_STRIDE];
    float* wvs = &pool[80 * KS_STRIDE];
    __shared__ int s_task;

    if (tid < 128)
        *(float4*)&wvs[tid * 4] = *(const float4*)&wv[tid * 4];

    const int kq_row = tid >> 4;
    const int kq_c4  = tid & 15;
    const int q_row  = tid >> 4;
    const int q_c4   = tid & 15;

    for (;;) {
        if (tid == 0) s_task = atomicAdd(&g_counter, 1);
        __syncthreads();
        const int t = s_task;
        if (t >= NTASKS) break;

        const int kh = t & 1;
        const int hh = (t >> 1) & 1;
        const int b  = (t >> 2) & 15;
        const int qt = t >> 6;
        const int vlen = valid_lens[b];
        const int kmax = min(KDIM, (vlen + 31) & ~31);
        const int kbase = kh * 64;

        if (kbase >= kmax) { __syncthreads(); continue; }

        const bool act1 = (kbase + 32 < vlen);
        const int hbase = hh * (HDIM / 2);

        const float* Qp = g_Qp + (b * QDIM + qt * 16) * HDIM;
        const float* Kp = g_Kp + (b * KDIM + kbase) * HDIM;

        float4 pk[2];
        float4 pq;

        const int krows = kmax - kbase;
#pragma unroll
        for (int i = 0; i < 2; i++)
            if (kq_row + 32 * i < krows)
                pk[i] = *(const float4*)&Kp[(kq_row + 32 * i) * HDIM + hbase + kq_c4 * 4];
        if (tid < 256)
            pq = *(const float4*)&Qp[q_row * HDIM + hbase + q_c4 * 4];

#pragma unroll
        for (int i = 0; i < 2; i++)
            if (kq_row + 32 * i < krows)
                *(float4*)&Ks[kq_row + 32 * i][kq_c4 * 4] = pk[i];
        if (tid < 256)
            *(float4*)&Qs[q_row][q_c4 * 4] = pq;
        __syncthreads();

        float s0 = 0.0f, s1 = 0.0f;

        const int NCH = (HDIM / 2) / HC;
        for (int hc = 0; hc < NCH; ++hc) {
            const int h0 = hbase + hc * HC;
            if (hc + 1 < NCH) {
                const int hn = h0 + HC;
#pragma unroll
                for (int i = 0; i < 2; i++)
                    if (kq_row + 32 * i < krows)
                        pk[i] = *(const float4*)&Kp[(kq_row + 32 * i) * HDIM + hn + kq_c4 * 4];
                if (tid < 256)
                    pq = *(const float4*)&Qp[q_row * HDIM + hn + q_c4 * 4];
            }

#pragma unroll
            for (int h4 = 0; h4 < HC / 4; ++h4) {
                const float4 w4 = *(const float4*)&wvs[h0 + h4 * 4];
                const float4 qa = *(const float4*)&Qs[w][h4 * 4];
                {
                    const float4 kv = *(const float4*)&Ks[tk][h4 * 4];
                    s0 = fmaf(tanh_fast(qa.x + kv.x), w4.x, s0);
                    s0 = fmaf(tanh_fast(qa.y + kv.y), w4.y, s0);
                    s0 = fmaf(tanh_fast(qa.z + kv.z), w4.z, s0);
                    s0 = fmaf(tanh_fast(qa.w + kv.w), w4.w, s0);
                }
                if (act1) {
                    const float4 kv = *(const float4*)&Ks[tk + 32][h4 * 4];
                    s1 = fmaf(tanh_fast(qa.x + kv.x), w4.x, s1);
                    s1 = fmaf(tanh_fast(qa.y + kv.y), w4.y, s1);
                    s1 = fmaf(tanh_fast(qa.z + kv.z), w4.z, s1);
                    s1 = fmaf(tanh_fast(qa.w + kv.w), w4.w, s1);
                }
            }
            __syncthreads();
            if (hc + 1 < NCH) {
#pragma unroll
                for (int i = 0; i < 2; i++)
                    if (kq_row + 32 * i < krows)
                        *(float4*)&Ks[kq_row + 32 * i][kq_c4 * 4] = pk[i];
                if (tid < 256)
                    *(float4*)&Qs[q_row][q_c4 * 4] = pq;
                __syncthreads();
            }
        }

        float* Sp = &g_S[hh][b][qt * 16 + w][0];
        Sp[kbase + tk] = s0;
        if (act1) Sp[kbase + tk + 32] = s1;
    }

    if (tid == 0) {
        __threadfence();
        const int d = atomicAdd(&g_done, 1);
        if (d == NBLOCKS - 1) { g_counter = 0; g_done = 0; }
    }
}

// ----------------------------------------------------------------------------
// softmax_av: sum partials, masked softmax, attn@V (unchanged).
// ----------------------------------------------------------------------------
__global__ __launch_bounds__(512, 1) void softmax_av(
    const float* __restrict__ values,
    const int* __restrict__ valid_lens,
    float* __restrict__ out)
{
    const int b  = blockIdx.y;
    const int qt = blockIdx.x;
    const int tid = threadIdx.x;
    const int tk  = tid & 31;
    const int w   = tid >> 5;

    __shared__ __align__(16) float attnT[128][20];

    const int vlen = valid_lens[b];
    const int kmax = min(KDIM, (vlen + 31) & ~31);

    const float* S0 = &g_S[0][b][qt * 16 + w][0];
    const float* S1 = &g_S[1][b][qt * 16 + w][0];

    float s[4];
#pragma unroll
    for (int j = 0; j < 4; j++) {
        const int k = tk + 32 * j;
        s[j] = (k < kmax) ? (S0[k] + S1[k]) : -1e6f;
        if (k >= vlen) s[j] = -1e6f;
    }

    float m = fmaxf(fmaxf(s[0], s[1]), fmaxf(s[2], s[3]));
#pragma unroll
    for (int off = 16; off > 0; off >>= 1)
        m = fmaxf(m, __shfl_xor_sync(0xFFFFFFFFu, m, off));
    float sum = 0.0f;
#pragma unroll
    for (int j = 0; j < 4; j++) {
        s[j] = __expf(s[j] - m);
        sum += s[j];
    }
#pragma unroll
    for (int off = 16; off > 0; off >>= 1)
        sum += __shfl_xor_sync(0xFFFFFFFFu, sum, off);
    const float rs = 1.0f / sum;
#pragma unroll
    for (int j = 0; j < 4; j++)
        attnT[tk + 32 * j][w] = s[j] * rs;
    __syncthreads();

    const int d = tid;
    const float* Vb = values + b * KDIM * DDIM + d;
    float acc[16];
#pragma unroll
    for (int q = 0; q < 16; q++) acc[q] = 0.0f;

    for (int k = 0; k < kmax; ++k) {
        const float v = Vb[k * DDIM];
        float a[16];
        *(float4*)&a[0]  = *(const float4*)&attnT[k][0];
        *(float4*)&a[4]  = *(const float4*)&attnT[k][4];
        *(float4*)&a[8]  = *(const float4*)&attnT[k][8];
        *(float4*)&a[12] = *(const float4*)&attnT[k][12];
#pragma unroll
        for (int q = 0; q < 16; q++)
            acc[q] = fmaf(a[q], v, acc[q]);
    }

    float* Ob = out + (b * QDIM + qt * 16) * DDIM + d;
#pragma unroll
    for (int q = 0; q < 16; q++)
        Ob[q * DDIM] = acc[q];
}

// ----------------------------------------------------------------------------
extern "C" void kernel_launch(void* const* d_in, const int* in_sizes, int n_in,
                              void* d_out, int out_size)
{
    const float* queries    = (const float*)d_in[0];
    const float* keys       = (const float*)d_in[1];
    const float* values     = (const float*)d_in[2];
    const int*   valid_lens = (const int*)d_in[3];
    const float* Wq         = (const float*)d_in[4];
    const float* Wk         = (const float*)d_in[5];
    const float* wv         = (const float*)d_in[6];
    float* out = (float*)d_out;

    prep<<<dim3(1280, 2), 256>>>(queries, keys, Wq, Wk);
    bf16_gemm<<<dim3(4, 16, 2), 256>>>();
    score_kernel<<<NBLOCKS, 512>>>(valid_lens, wv);
    softmax_av<<<dim3(8, 16), 512>>>(values, valid_lens, out);
}

// round 14
// speedup vs baseline: 1.5053x; 1.0250x over previous
#include <cuda_runtime.h>
#include <cuda_bf16.h>
#include <cstdint>

// ============================================================================
// AdditiveAttention: out = softmax_mask( sum_h tanh(Q@Wq + K@Wk) * wv ) @ V
// B=16, Q=128, K=128, D=512, H=512
//  prep          : fused fp32->bf16 hi/lo split of A (row-major) and W^T
//  bf16_gemm     : Qp/Kp = A@W via mma.sync m16n8k16 bf16, 3-term split,
//                  register-prefetch double-buffered k-chunks
//  score_kernel  : persistent 296 x 512thr (2 blocks/SM), 512 tasks
//                  (b, 16 q-rows, h-half, k-half); empty-task skip
//  softmax_av    : grid (16 q-octets, 16 b) x 512thr, 2 blocks/SM, MLP-4 AV
// ============================================================================

#define BDIM 16
#define QDIM 128
#define KDIM 128
#define DDIM 512
#define HDIM 512
#define NTASKS 512
#define NBLOCKS 296

__device__ float g_Qp[BDIM * QDIM * HDIM];     // 4 MB
__device__ float g_Kp[BDIM * KDIM * HDIM];     // 4 MB
__device__ float g_S[2][BDIM][QDIM][KDIM];     // partial scores, 2 MB
__device__ int   g_counter;
__device__ int   g_done;

__device__ unsigned short g_Ah[2][2048 * 512];
__device__ unsigned short g_Al[2][2048 * 512];
__device__ unsigned short g_Bth[2][512 * 512];   // W^T : [n][k]
__device__ unsigned short g_Btl[2][512 * 512];

__device__ __forceinline__ float tanh_fast(float x) {
    float y;
    asm("tanh.approx.f32 %0, %1;" : "=f"(y) : "f"(x));
    return y;
}
__device__ __forceinline__ void bf16_split(float x, unsigned short& hi, unsigned short& lo) {
    __nv_bfloat16 h = __float2bfloat16_rn(x);
    __nv_bfloat16 l = __float2bfloat16_rn(x - __bfloat162float(h));
    hi = __bfloat16_as_ushort(h);
    lo = __bfloat16_as_ushort(l);
}
__device__ __forceinline__ void ldsm_x4(uint32_t* r, uint32_t addr) {
    asm volatile("ldmatrix.sync.aligned.m8n8.x4.shared.b16 {%0,%1,%2,%3}, [%4];"
        : "=r"(r[0]), "=r"(r[1]), "=r"(r[2]), "=r"(r[3]) : "r"(addr));
}
__device__ __forceinline__ void mma_bf16(float* c, const uint32_t* a, const uint32_t* b) {
    asm volatile("mma.sync.aligned.m16n8k16.row.col.f32.bf16.bf16.f32 "
        "{%0,%1,%2,%3}, {%4,%5,%6,%7}, {%8,%9}, {%0,%1,%2,%3};"
        : "+f"(c[0]), "+f"(c[1]), "+f"(c[2]), "+f"(c[3])
        : "r"(a[0]), "r"(a[1]), "r"(a[2]), "r"(a[3]), "r"(b[0]), "r"(b[1]));
}

// ----------------------------------------------------------------------------
// prep: fused. grid (1280, 2) x 256 threads.
// ----------------------------------------------------------------------------
__global__ void prep(const float* __restrict__ Aq, const float* __restrict__ Ak,
                     const float* __restrict__ Wq, const float* __restrict__ Wk)
{
    __shared__ float tile[32][33];
    const int z = blockIdx.y;
    const int bx = blockIdx.x;
    const int tid = threadIdx.x;

    if (bx < 1024) {
        const float* A = z ? Ak : Aq;
        const int idx = bx * 256 + tid;
        const float4 v = ((const float4*)A)[idx];
        ushort4 h, l;
        bf16_split(v.x, h.x, l.x);
        bf16_split(v.y, h.y, l.y);
        bf16_split(v.z, h.z, l.z);
        bf16_split(v.w, h.w, l.w);
        ((ushort4*)g_Ah[z])[idx] = h;
        ((ushort4*)g_Al[z])[idx] = l;
    } else {
        const float* W = z ? Wk : Wq;
        const int wb = bx - 1024;
        const int n0 = (wb & 15) * 32;
        const int k0 = (wb >> 4) * 32;
        const int tx = tid & 31;
        const int ty = tid >> 5;
#pragma unroll
        for (int i = 0; i < 4; i++) {
            const int r = ty + i * 8;
            tile[r][tx] = W[(k0 + r) * 512 + n0 + tx];
        }
        __syncthreads();
#pragma unroll
        for (int i = 0; i < 4; i++) {
            const int r = ty + i * 8;
            unsigned short hi, lo;
            bf16_split(tile[tx][r], hi, lo);
            g_Bth[z][(n0 + r) * 512 + k0 + tx] = hi;
            g_Btl[z][(n0 + r) * 512 + k0 + tx] = lo;
        }
    }
}

// ----------------------------------------------------------------------------
// bf16_gemm (unchanged from R13)
// ----------------------------------------------------------------------------
#define KC 32
#define AST 40

__global__ __launch_bounds__(256, 1) void bf16_gemm()
{
    const int z  = blockIdx.z;
    const int m0 = blockIdx.y * 128;
    const int n0 = blockIdx.x * 128;

    const unsigned short* Ah = g_Ah[z];
    const unsigned short* Al = g_Al[z];
    const unsigned short* Bh = g_Bth[z];
    const unsigned short* Bl = g_Btl[z];
    float* C = z ? g_Kp : g_Qp;

    __shared__ __align__(16) unsigned short sAh[128 * AST];
    __shared__ __align__(16) unsigned short sAl[128 * AST];
    __shared__ __align__(16) unsigned short sBh[128 * AST];
    __shared__ __align__(16) unsigned short sBl[128 * AST];

    const int tid  = threadIdx.x;
    const int lane = tid & 31;
    const int wid  = tid >> 5;
    const int warp_m = wid & 3;
    const int warp_n = wid >> 2;

    const int lr = tid >> 1;
    const int lc = (tid & 1) * 16;

    const int grp = lane >> 3, l8 = lane & 7;
    const uint32_t sAh_b = (uint32_t)__cvta_generic_to_shared(sAh);
    const uint32_t sAl_b = (uint32_t)__cvta_generic_to_shared(sAl);
    const uint32_t sBh_b = (uint32_t)__cvta_generic_to_shared(sBh);
    const uint32_t sBl_b = (uint32_t)__cvta_generic_to_shared(sBl);
    const uint32_t aoff = ((warp_m * 32 + (grp & 1) * 8 + l8) * AST + (grp >> 1) * 8) * 2;
    const uint32_t boff = ((warp_n * 64 + (grp >> 1) * 8 + l8) * AST + (grp & 1) * 8) * 2;

    float acc[2][8][4];
#pragma unroll
    for (int mt = 0; mt < 2; mt++)
#pragma unroll
        for (int nt = 0; nt < 8; nt++)
#pragma unroll
            for (int i = 0; i < 4; i++) acc[mt][nt][i] = 0.0f;

    const int ga0 = (m0 + lr) * 512 + lc;
    const int gb0 = (n0 + lr) * 512 + lc;

    uint4 rah0, rah1, ral0, ral1, rbh0, rbh1, rbl0, rbl1;
    rah0 = *(const uint4*)&Ah[ga0];     rah1 = *(const uint4*)&Ah[ga0 + 8];
    ral0 = *(const uint4*)&Al[ga0];     ral1 = *(const uint4*)&Al[ga0 + 8];
    rbh0 = *(const uint4*)&Bh[gb0];     rbh1 = *(const uint4*)&Bh[gb0 + 8];
    rbl0 = *(const uint4*)&Bl[gb0];     rbl1 = *(const uint4*)&Bl[gb0 + 8];

    const int NKC = 512 / KC;
    for (int it = 0; it < NKC; ++it) {
        *(uint4*)&sAh[lr * AST + lc]     = rah0;
        *(uint4*)&sAh[lr * AST + lc + 8] = rah1;
        *(uint4*)&sAl[lr * AST + lc]     = ral0;
        *(uint4*)&sAl[lr * AST + lc + 8] = ral1;
        *(uint4*)&sBh[lr * AST + lc]     = rbh0;
        *(uint4*)&sBh[lr * AST + lc + 8] = rbh1;
        *(uint4*)&sBl[lr * AST + lc]     = rbl0;
        *(uint4*)&sBl[lr * AST + lc + 8] = rbl1;
        __syncthreads();

        if (it + 1 < NKC) {
            const int ga = ga0 + (it + 1) * KC;
            const int gb = gb0 + (it + 1) * KC;
            rah0 = *(const uint4*)&Ah[ga];     rah1 = *(const uint4*)&Ah[ga + 8];
            ral0 = *(const uint4*)&Al[ga];     ral1 = *(const uint4*)&Al[ga + 8];
            rbh0 = *(const uint4*)&Bh[gb];     rbh1 = *(const uint4*)&Bh[gb + 8];
            rbl0 = *(const uint4*)&Bl[gb];     rbl1 = *(const uint4*)&Bl[gb + 8];
        }

#pragma unroll
        for (int ks = 0; ks < KC; ks += 16) {
            uint32_t ah[2][4], al[2][4], bh[4][4], bl[4][4];
#pragma unroll
            for (int mt = 0; mt < 2; mt++) {
                ldsm_x4(ah[mt], sAh_b + aoff + mt * (16 * AST * 2) + ks * 2);
                ldsm_x4(al[mt], sAl_b + aoff + mt * (16 * AST * 2) + ks * 2);
            }
#pragma unroll
            for (int j = 0; j < 4; j++) {
                ldsm_x4(bh[j], sBh_b + boff + j * (16 * AST * 2) + ks * 2);
                ldsm_x4(bl[j], sBl_b + boff + j * (16 * AST * 2) + ks * 2);
            }
#pragma unroll
            for (int mt = 0; mt < 2; mt++)
#pragma unroll
                for (int nt = 0; nt < 8; nt++) {
                    const uint32_t* ph = &bh[nt >> 1][(nt & 1) * 2];
                    const uint32_t* pl = &bl[nt >> 1][(nt & 1) * 2];
                    mma_bf16(acc[mt][nt], ah[mt], ph);
                    mma_bf16(acc[mt][nt], ah[mt], pl);
                    mma_bf16(acc[mt][nt], al[mt], ph);
                }
        }
        __syncthreads();
    }

    const int g = lane >> 2, t = lane & 3;
#pragma unroll
    for (int mt = 0; mt < 2; mt++) {
        const int row = m0 + warp_m * 32 + mt * 16 + g;
#pragma unroll
        for (int nt = 0; nt < 8; nt++) {
            const int col = n0 + warp_n * 64 + nt * 8 + t * 2;
            *(float2*)&C[row * 512 + col]       = make_float2(acc[mt][nt][0], acc[mt][nt][1]);
            *(float2*)&C[(row + 8) * 512 + col] = make_float2(acc[mt][nt][2], acc[mt][nt][3]);
        }
    }
}

// ----------------------------------------------------------------------------
// score_kernel (unchanged from R12/R13)
// ----------------------------------------------------------------------------
#define HC 64
#define KS_STRIDE 68
#define POOL_FLOATS (64 * KS_STRIDE + 16 * KS_STRIDE + HDIM)   // 23.8KB

__global__ __launch_bounds__(512, 2) void score_kernel(
    const int* __restrict__ valid_lens,
    const float* __restrict__ wv)
{
    const int tid = threadIdx.x;
    const int tk  = tid & 31;
    const int w   = tid >> 5;

    __shared__ __align__(16) float pool[POOL_FLOATS];
    float (*Ks)[KS_STRIDE] = (float(*)[KS_STRIDE])&pool[0];
    float (*Qs)[KS_STRIDE] = (float(*)[KS_STRIDE])&pool[64 * KS_STRIDE];
    float* wvs = &pool[80 * KS_STRIDE];
    __shared__ int s_task;

    if (tid < 128)
        *(float4*)&wvs[tid * 4] = *(const float4*)&wv[tid * 4];

    const int kq_row = tid >> 4;
    const int kq_c4  = tid & 15;
    const int q_row  = tid >> 4;
    const int q_c4   = tid & 15;

    for (;;) {
        if (tid == 0) s_task = atomicAdd(&g_counter, 1);
        __syncthreads();
        const int t = s_task;
        if (t >= NTASKS) break;

        const int kh = t & 1;
        const int hh = (t >> 1) & 1;
        const int b  = (t >> 2) & 15;
        const int qt = t >> 6;
        const int vlen = valid_lens[b];
        const int kmax = min(KDIM, (vlen + 31) & ~31);
        const int kbase = kh * 64;

        if (kbase >= kmax) { __syncthreads(); continue; }

        const bool act1 = (kbase + 32 < vlen);
        const int hbase = hh * (HDIM / 2);

        const float* Qp = g_Qp + (b * QDIM + qt * 16) * HDIM;
        const float* Kp = g_Kp + (b * KDIM + kbase) * HDIM;

        float4 pk[2];
        float4 pq;

        const int krows = kmax - kbase;
#pragma unroll
        for (int i = 0; i < 2; i++)
            if (kq_row + 32 * i < krows)
                pk[i] = *(const float4*)&Kp[(kq_row + 32 * i) * HDIM + hbase + kq_c4 * 4];
        if (tid < 256)
            pq = *(const float4*)&Qp[q_row * HDIM + hbase + q_c4 * 4];

#pragma unroll
        for (int i = 0; i < 2; i++)
            if (kq_row + 32 * i < krows)
                *(float4*)&Ks[kq_row + 32 * i][kq_c4 * 4] = pk[i];
        if (tid < 256)
            *(float4*)&Qs[q_row][q_c4 * 4] = pq;
        __syncthreads();

        float s0 = 0.0f, s1 = 0.0f;

        const int NCH = (HDIM / 2) / HC;
        for (int hc = 0; hc < NCH; ++hc) {
            const int h0 = hbase + hc * HC;
            if (hc + 1 < NCH) {
                const int hn = h0 + HC;
#pragma unroll
                for (int i = 0; i < 2; i++)
                    if (kq_row + 32 * i < krows)
                        pk[i] = *(const float4*)&Kp[(kq_row + 32 * i) * HDIM + hn + kq_c4 * 4];
                if (tid < 256)
                    pq = *(const float4*)&Qp[q_row * HDIM + hn + q_c4 * 4];
            }

#pragma unroll
            for (int h4 = 0; h4 < HC / 4; ++h4) {
                const float4 w4 = *(const float4*)&wvs[h0 + h4 * 4];
                const float4 qa = *(const float4*)&Qs[w][h4 * 4];
                {
                    const float4 kv = *(const float4*)&Ks[tk][h4 * 4];
                    s0 = fmaf(tanh_fast(qa.x + kv.x), w4.x, s0);
                    s0 = fmaf(tanh_fast(qa.y + kv.y), w4.y, s0);
                    s0 = fmaf(tanh_fast(qa.z + kv.z), w4.z, s0);
                    s0 = fmaf(tanh_fast(qa.w + kv.w), w4.w, s0);
                }
                if (act1) {
                    const float4 kv = *(const float4*)&Ks[tk + 32][h4 * 4];
                    s1 = fmaf(tanh_fast(qa.x + kv.x), w4.x, s1);
                    s1 = fmaf(tanh_fast(qa.y + kv.y), w4.y, s1);
                    s1 = fmaf(tanh_fast(qa.z + kv.z), w4.z, s1);
                    s1 = fmaf(tanh_fast(qa.w + kv.w), w4.w, s1);
                }
            }
            __syncthreads();
            if (hc + 1 < NCH) {
#pragma unroll
                for (int i = 0; i < 2; i++)
                    if (kq_row + 32 * i < krows)
                        *(float4*)&Ks[kq_row + 32 * i][kq_c4 * 4] = pk[i];
                if (tid < 256)
                    *(float4*)&Qs[q_row][q_c4 * 4] = pq;
                __syncthreads();
            }
        }

        float* Sp = &g_S[hh][b][qt * 16 + w][0];
        Sp[kbase + tk] = s0;
        if (act1) Sp[kbase + tk + 32] = s1;
    }

    if (tid == 0) {
        __threadfence();
        const int d = atomicAdd(&g_done, 1);
        if (d == NBLOCKS - 1) { g_counter = 0; g_done = 0; }
    }
}

// ----------------------------------------------------------------------------
// softmax_av: grid (16 q-octets, 16 b) x 512 thr, 2 blocks/SM.
// Softmax: warp w -> row w>>1, k-half w&1; cross-pair merge via pm/ps.
// AV: thread = 1 d-column, acc[8], k-loop unrolled x4 (MLP=4).
// ----------------------------------------------------------------------------
__global__ __launch_bounds__(512, 2) void softmax_av(
    const float* __restrict__ values,
    const int* __restrict__ valid_lens,
    float* __restrict__ out)
{
    const int b  = blockIdx.y;
    const int qo = blockIdx.x;        // 0..15 -> q-rows [qo*8, +8)
    const int tid = threadIdx.x;
    const int tk  = tid & 31;
    const int w   = tid >> 5;         // 0..15
    const int row = w >> 1;           // 0..7
    const int w2  = w & 1;            // k-half

    __shared__ __align__(16) float attnT[128][12];
    __shared__ float pm[8][2], ps[8][2];

    const int vlen = valid_lens[b];
    const int kmax = min(KDIM, (vlen + 31) & ~31);

    const int qrow = qo * 8 + row;
    const float* S0 = &g_S[0][b][qrow][0];
    const float* S1 = &g_S[1][b][qrow][0];

    const int k0 = tk + 64 * w2;
    const int k1 = tk + 32 + 64 * w2;
    float s0 = (k0 < kmax) ? (S0[k0] + S1[k0]) : -1e6f;
    float s1 = (k1 < kmax) ? (S0[k1] + S1[k1]) : -1e6f;
    if (k0 >= vlen) s0 = -1e6f;
    if (k1 >= vlen) s1 = -1e6f;

    float m = fmaxf(s0, s1);
#pragma unroll
    for (int off = 16; off > 0; off >>= 1)
        m = fmaxf(m, __shfl_xor_sync(0xFFFFFFFFu, m, off));
    const float e0 = __expf(s0 - m), e1 = __expf(s1 - m);
    float sum = e0 + e1;
#pragma unroll
    for (int off = 16; off > 0; off >>= 1)
        sum += __shfl_xor_sync(0xFFFFFFFFu, sum, off);
    if (tk == 0) { pm[row][w2] = m; ps[row][w2] = sum; }
    __syncthreads();

    const float m0p = pm[row][0], m1p = pm[row][1];
    const float mg = fmaxf(m0p, m1p);
    const float sg = ps[row][0] * __expf(m0p - mg) + ps[row][1] * __expf(m1p - mg);
    const float rs = __expf(pm[row][w2] - mg) / sg;
    attnT[k0][row] = e0 * rs;
    attnT[k1][row] = e1 * rs;
    __syncthreads();

    // ---- AV: out[8,512] = attn[8,kmax] @ V[kmax,512], unroll 4 (MLP=4) ----
    const int d = tid;
    const float* Vb = values + b * KDIM * DDIM + d;
    float acc[8];
#pragma unroll
    for (int q = 0; q < 8; q++) acc[q] = 0.0f;

    for (int k = 0; k < kmax; k += 4) {
        const float v0 = Vb[(k + 0) * DDIM];
        const float v1 = Vb[(k + 1) * DDIM];
        const float v2 = Vb[(k + 2) * DDIM];
        const float v3 = Vb[(k + 3) * DDIM];
        float a0[8], a1[8], a2[8], a3[8];
        *(float4*)&a0[0] = *(const float4*)&attnT[k + 0][0];
        *(float4*)&a0[4] = *(const float4*)&attnT[k + 0][4];
        *(float4*)&a1[0] = *(const float4*)&attnT[k + 1][0];
        *(float4*)&a1[4] = *(const float4*)&attnT[k + 1][4];
        *(float4*)&a2[0] = *(const float4*)&attnT[k + 2][0];
        *(float4*)&a2[4] = *(const float4*)&attnT[k + 2][4];
        *(float4*)&a3[0] = *(const float4*)&attnT[k + 3][0];
        *(float4*)&a3[4] = *(const float4*)&attnT[k + 3][4];
#pragma unroll
        for (int q = 0; q < 8; q++) {
            acc[q] = fmaf(a0[q], v0, acc[q]);
            acc[q] = fmaf(a1[q], v1, acc[q]);
            acc[q] = fmaf(a2[q], v2, acc[q]);
            acc[q] = fmaf(a3[q], v3, acc[q]);
        }
    }

    float* Ob = out + (b * QDIM + qo * 8) * DDIM + d;
#pragma unroll
    for (int q = 0; q < 8; q++)
        Ob[q * DDIM] = acc[q];
}

// ----------------------------------------------------------------------------
extern "C" void kernel_launch(void* const* d_in, const int* in_sizes, int n_in,
                              void* d_out, int out_size)
{
    const float* queries    = (const float*)d_in[0];
    const float* keys       = (const float*)d_in[1];
    const float* values     = (const float*)d_in[2];
    const int*   valid_lens = (const int*)d_in[3];
    const float* Wq         = (const float*)d_in[4];
    const float* Wk         = (const float*)d_in[5];
    const float* wv         = (const float*)d_in[6];
    float* out = (float*)d_out;

    prep<<<dim3(1280, 2), 256>>>(queries, keys, Wq, Wk);
    bf16_gemm<<<dim3(4, 16, 2), 256>>>();
    score_kernel<<<NBLOCKS, 512>>>(valid_lens, wv);
    softmax_av<<<dim3(16, 16), 512>>>(values, valid_lens, out);
}

// round 15
// speedup vs baseline: 1.5434x; 1.0253x over previous
#include <cuda_runtime.h>
#include <cuda_bf16.h>
#include <cstdint>

// ============================================================================
// AdditiveAttention: out = softmax_mask( sum_h tanh(Q@Wq + K@Wk) * wv ) @ V
// B=16, Q=128, K=128, D=512, H=512
//  prep          : W^T fp32->bf16 hi/lo split only (A split moved into gemm)
//  bf16_gemm     : Qp/Kp = A@W, mma m16n8k16 bf16 3-term split; A loaded f32
//                  from inputs and split in registers; reg-prefetch dbuf
//  score_kernel  : persistent 296 x 512thr (2 blocks/SM), 1024 tasks
//                  (b, 16 q-rows, h-quarter, k-half); empty-task skip
//  softmax_av    : grid (16 q-octets, 16 b) x 512thr, sums 4 partials, MLP-4 AV
// ============================================================================

#define BDIM 16
#define QDIM 128
#define KDIM 128
#define DDIM 512
#define HDIM 512
#define NTASKS 1024
#define NBLOCKS 296

__device__ float g_Qp[BDIM * QDIM * HDIM];     // 4 MB
__device__ float g_Kp[BDIM * KDIM * HDIM];     // 4 MB
__device__ float g_S[4][BDIM][QDIM][KDIM];     // partial scores, 4 MB
__device__ int   g_counter;
__device__ int   g_done;

__device__ unsigned short g_Bth[2][512 * 512];   // W^T : [n][k]
__device__ unsigned short g_Btl[2][512 * 512];

__device__ __forceinline__ float tanh_fast(float x) {
    float y;
    asm("tanh.approx.f32 %0, %1;" : "=f"(y) : "f"(x));
    return y;
}
__device__ __forceinline__ void bf16_split(float x, unsigned short& hi, unsigned short& lo) {
    __nv_bfloat16 h = __float2bfloat16_rn(x);
    __nv_bfloat16 l = __float2bfloat16_rn(x - __bfloat162float(h));
    hi = __bfloat16_as_ushort(h);
    lo = __bfloat16_as_ushort(l);
}
__device__ __forceinline__ void ldsm_x4(uint32_t* r, uint32_t addr) {
    asm volatile("ldmatrix.sync.aligned.m8n8.x4.shared.b16 {%0,%1,%2,%3}, [%4];"
        : "=r"(r[0]), "=r"(r[1]), "=r"(r[2]), "=r"(r[3]) : "r"(addr));
}
__device__ __forceinline__ void mma_bf16(float* c, const uint32_t* a, const uint32_t* b) {
    asm volatile("mma.sync.aligned.m16n8k16.row.col.f32.bf16.bf16.f32 "
        "{%0,%1,%2,%3}, {%4,%5,%6,%7}, {%8,%9}, {%0,%1,%2,%3};"
        : "+f"(c[0]), "+f"(c[1]), "+f"(c[2]), "+f"(c[3])
        : "r"(a[0]), "r"(a[1]), "r"(a[2]), "r"(a[3]), "r"(b[0]), "r"(b[1]));
}

// ----------------------------------------------------------------------------
// prep: W^T split only. grid (256, 2) x 256 threads; block = one 32x32 tile.
// ----------------------------------------------------------------------------
__global__ void prep(const float* __restrict__ Wq, const float* __restrict__ Wk)
{
    __shared__ float tile[32][33];
    const int z = blockIdx.y;
    const float* W = z ? Wk : Wq;
    const int wb = blockIdx.x;
    const int n0 = (wb & 15) * 32;
    const int k0 = (wb >> 4) * 32;
    const int tid = threadIdx.x;
    const int tx = tid & 31;
    const int ty = tid >> 5;
#pragma unroll
    for (int i = 0; i < 4; i++) {
        const int r = ty + i * 8;
        tile[r][tx] = W[(k0 + r) * 512 + n0 + tx];
    }
    __syncthreads();
#pragma unroll
    for (int i = 0; i < 4; i++) {
        const int r = ty + i * 8;
        unsigned short hi, lo;
        bf16_split(tile[tx][r], hi, lo);
        g_Bth[z][(n0 + r) * 512 + k0 + tx] = hi;
        g_Btl[z][(n0 + r) * 512 + k0 + tx] = lo;
    }
}

// ----------------------------------------------------------------------------
// bf16_gemm: C[2048,512] = A@W per z. 128x128 tile, KC=32, 256 thr (8 warps
// as 4x2), warp tile 32x64. A loaded f32 and split in registers.
// ----------------------------------------------------------------------------
#define KC 32
#define AST 40

__global__ __launch_bounds__(256, 1) void bf16_gemm(
    const float* __restrict__ Aq, const float* __restrict__ Ak)
{
    const int z  = blockIdx.z;
    const int m0 = blockIdx.y * 128;
    const int n0 = blockIdx.x * 128;

    const float* Af = z ? Ak : Aq;
    const unsigned short* Bh = g_Bth[z];
    const unsigned short* Bl = g_Btl[z];
    float* C = z ? g_Kp : g_Qp;

    __shared__ __align__(16) unsigned short sAh[128 * AST];
    __shared__ __align__(16) unsigned short sAl[128 * AST];
    __shared__ __align__(16) unsigned short sBh[128 * AST];
    __shared__ __align__(16) unsigned short sBl[128 * AST];

    const int tid  = threadIdx.x;
    const int lane = tid & 31;
    const int wid  = tid >> 5;
    const int warp_m = wid & 3;
    const int warp_n = wid >> 2;

    const int lr = tid >> 1;
    const int lc = (tid & 1) * 16;

    const int grp = lane >> 3, l8 = lane & 7;
    const uint32_t sAh_b = (uint32_t)__cvta_generic_to_shared(sAh);
    const uint32_t sAl_b = (uint32_t)__cvta_generic_to_shared(sAl);
    const uint32_t sBh_b = (uint32_t)__cvta_generic_to_shared(sBh);
    const uint32_t sBl_b = (uint32_t)__cvta_generic_to_shared(sBl);
    const uint32_t aoff = ((warp_m * 32 + (grp & 1) * 8 + l8) * AST + (grp >> 1) * 8) * 2;
    const uint32_t boff = ((warp_n * 64 + (grp >> 1) * 8 + l8) * AST + (grp & 1) * 8) * 2;

    float acc[2][8][4];
#pragma unroll
    for (int mt = 0; mt < 2; mt++)
#pragma unroll
        for (int nt = 0; nt < 8; nt++)
#pragma unroll
            for (int i = 0; i < 4; i++) acc[mt][nt][i] = 0.0f;

    const int ga0 = (m0 + lr) * 512 + lc;
    const int gb0 = (n0 + lr) * 512 + lc;

    // prefetch chunk 0: A as f32 (4 float4), B as packed bf16 (4 uint4)
    float fa[16];
    uint4 rbh0, rbh1, rbl0, rbl1;
#pragma unroll
    for (int i = 0; i < 4; i++)
        *(float4*)&fa[i * 4] = *(const float4*)&Af[ga0 + i * 4];
    rbh0 = *(const uint4*)&Bh[gb0];     rbh1 = *(const uint4*)&Bh[gb0 + 8];
    rbl0 = *(const uint4*)&Bl[gb0];     rbl1 = *(const uint4*)&Bl[gb0 + 8];

    const int NKC = 512 / KC;
    for (int it = 0; it < NKC; ++it) {
        // split A regs and store chunk -> smem
        {
            unsigned short ha[16], la[16];
#pragma unroll
            for (int i = 0; i < 16; i++) bf16_split(fa[i], ha[i], la[i]);
            *(uint4*)&sAh[lr * AST + lc]     = *(uint4*)&ha[0];
            *(uint4*)&sAh[lr * AST + lc + 8] = *(uint4*)&ha[8];
            *(uint4*)&sAl[lr * AST + lc]     = *(uint4*)&la[0];
            *(uint4*)&sAl[lr * AST + lc + 8] = *(uint4*)&la[8];
        }
        *(uint4*)&sBh[lr * AST + lc]     = rbh0;
        *(uint4*)&sBh[lr * AST + lc + 8] = rbh1;
        *(uint4*)&sBl[lr * AST + lc]     = rbl0;
        *(uint4*)&sBl[lr * AST + lc + 8] = rbl1;
        __syncthreads();

        if (it + 1 < NKC) {
            const int ga = ga0 + (it + 1) * KC;
            const int gb = gb0 + (it + 1) * KC;
#pragma unroll
            for (int i = 0; i < 4; i++)
                *(float4*)&fa[i * 4] = *(const float4*)&Af[ga + i * 4];
            rbh0 = *(const uint4*)&Bh[gb];     rbh1 = *(const uint4*)&Bh[gb + 8];
            rbl0 = *(const uint4*)&Bl[gb];     rbl1 = *(const uint4*)&Bl[gb + 8];
        }

#pragma unroll
        for (int ks = 0; ks < KC; ks += 16) {
            uint32_t ah[2][4], al[2][4], bh[4][4], bl[4][4];
#pragma unroll
            for (int mt = 0; mt < 2; mt++) {
                ldsm_x4(ah[mt], sAh_b + aoff + mt * (16 * AST * 2) + ks * 2);
                ldsm_x4(al[mt], sAl_b + aoff + mt * (16 * AST * 2) + ks * 2);
            }
#pragma unroll
            for (int j = 0; j < 4; j++) {
                ldsm_x4(bh[j], sBh_b + boff + j * (16 * AST * 2) + ks * 2);
                ldsm_x4(bl[j], sBl_b + boff + j * (16 * AST * 2) + ks * 2);
            }
#pragma unroll
            for (int mt = 0; mt < 2; mt++)
#pragma unroll
                for (int nt = 0; nt < 8; nt++) {
                    const uint32_t* ph = &bh[nt >> 1][(nt & 1) * 2];
                    const uint32_t* pl = &bl[nt >> 1][(nt & 1) * 2];
                    mma_bf16(acc[mt][nt], ah[mt], ph);
                    mma_bf16(acc[mt][nt], ah[mt], pl);
                    mma_bf16(acc[mt][nt], al[mt], ph);
                }
        }
        __syncthreads();
    }

    const int g = lane >> 2, t = lane & 3;
#pragma unroll
    for (int mt = 0; mt < 2; mt++) {
        const int row = m0 + warp_m * 32 + mt * 16 + g;
#pragma unroll
        for (int nt = 0; nt < 8; nt++) {
            const int col = n0 + warp_n * 64 + nt * 8 + t * 2;
            *(float2*)&C[row * 512 + col]       = make_float2(acc[mt][nt][0], acc[mt][nt][1]);
            *(float2*)&C[(row + 8) * 512 + col] = make_float2(acc[mt][nt][2], acc[mt][nt][3]);
        }
    }
}

// ----------------------------------------------------------------------------
// score_kernel: partial scores. 1024 tasks: kh = t&1, hq = (t>>1)&3,
// b = (t>>3)&15, qt = t>>7. h-quarter = 2 chunks of 64, reg dbuf.
// Writes S[hq][b][qt*16+w][kh*64 + {tk, tk+32}].
// ----------------------------------------------------------------------------
#define HC 64
#define KS_STRIDE 68
#define POOL_FLOATS (64 * KS_STRIDE + 16 * KS_STRIDE + HDIM)   // 23.8KB

__global__ __launch_bounds__(512, 2) void score_kernel(
    const int* __restrict__ valid_lens,
    const float* __restrict__ wv)
{
    const int tid = threadIdx.x;
    const int tk  = tid & 31;
    const int w   = tid >> 5;

    __shared__ __align__(16) float pool[POOL_FLOATS];
    float (*Ks)[KS_STRIDE] = (float(*)[KS_STRIDE])&pool[0];
    float (*Qs)[KS_STRIDE] = (float(*)[KS_STRIDE])&pool[64 * KS_STRIDE];
    float* wvs = &pool[80 * KS_STRIDE];
    __shared__ int s_task;

    if (tid < 128)
        *(float4*)&wvs[tid * 4] = *(const float4*)&wv[tid * 4];

    const int kq_row = tid >> 4;
    const int kq_c4  = tid & 15;
    const int q_row  = tid >> 4;
    const int q_c4   = tid & 15;

    for (;;) {
        if (tid == 0) s_task = atomicAdd(&g_counter, 1);
        __syncthreads();
        const int t = s_task;
        if (t >= NTASKS) break;

        const int kh = t & 1;
        const int hq = (t >> 1) & 3;
        const int b  = (t >> 3) & 15;
        const int qt = t >> 7;                 // 0..7
        const int vlen = valid_lens[b];
        const int kmax = min(KDIM, (vlen + 31) & ~31);
        const int kbase = kh * 64;

        if (kbase >= kmax) { __syncthreads(); continue; }

        const bool act1 = (kbase + 32 < vlen);
        const int hbase = hq * (HDIM / 4);     // 0,128,256,384

        const float* Qp = g_Qp + (b * QDIM + qt * 16) * HDIM;
        const float* Kp = g_Kp + (b * KDIM + kbase) * HDIM;

        float4 pk[2];
        float4 pq;

        const int krows = kmax - kbase;
#pragma unroll
        for (int i = 0; i < 2; i++)
            if (kq_row + 32 * i < krows)
                pk[i] = *(const float4*)&Kp[(kq_row + 32 * i) * HDIM + hbase + kq_c4 * 4];
        if (tid < 256)
            pq = *(const float4*)&Qp[q_row * HDIM + hbase + q_c4 * 4];

#pragma unroll
        for (int i = 0; i < 2; i++)
            if (kq_row + 32 * i < krows)
                *(float4*)&Ks[kq_row + 32 * i][kq_c4 * 4] = pk[i];
        if (tid < 256)
            *(float4*)&Qs[q_row][q_c4 * 4] = pq;
        __syncthreads();

        float s0 = 0.0f, s1 = 0.0f;

        const int NCH = (HDIM / 4) / HC;   // 2
        for (int hc = 0; hc < NCH; ++hc) {
            const int h0 = hbase + hc * HC;
            if (hc + 1 < NCH) {
                const int hn = h0 + HC;
#pragma unroll
                for (int i = 0; i < 2; i++)
                    if (kq_row + 32 * i < krows)
                        pk[i] = *(const float4*)&Kp[(kq_row + 32 * i) * HDIM + hn + kq_c4 * 4];
                if (tid < 256)
                    pq = *(const float4*)&Qp[q_row * HDIM + hn + q_c4 * 4];
            }

#pragma unroll
            for (int h4 = 0; h4 < HC / 4; ++h4) {
                const float4 w4 = *(const float4*)&wvs[h0 + h4 * 4];
                const float4 qa = *(const float4*)&Qs[w][h4 * 4];
                {
                    const float4 kv = *(const float4*)&Ks[tk][h4 * 4];
                    s0 = fmaf(tanh_fast(qa.x + kv.x), w4.x, s0);
                    s0 = fmaf(tanh_fast(qa.y + kv.y), w4.y, s0);
                    s0 = fmaf(tanh_fast(qa.z + kv.z), w4.z, s0);
                    s0 = fmaf(tanh_fast(qa.w + kv.w), w4.w, s0);
                }
                if (act1) {
                    const float4 kv = *(const float4*)&Ks[tk + 32][h4 * 4];
                    s1 = fmaf(tanh_fast(qa.x + kv.x), w4.x, s1);
                    s1 = fmaf(tanh_fast(qa.y + kv.y), w4.y, s1);
                    s1 = fmaf(tanh_fast(qa.z + kv.z), w4.z, s1);
                    s1 = fmaf(tanh_fast(qa.w + kv.w), w4.w, s1);
                }
            }
            __syncthreads();
            if (hc + 1 < NCH) {
#pragma unroll
                for (int i = 0; i < 2; i++)
                    if (kq_row + 32 * i < krows)
                        *(float4*)&Ks[kq_row + 32 * i][kq_c4 * 4] = pk[i];
                if (tid < 256)
                    *(float4*)&Qs[q_row][q_c4 * 4] = pq;
                __syncthreads();
            }
        }

        float* Sp = &g_S[hq][b][qt * 16 + w][0];
        Sp[kbase + tk] = s0;
        if (act1) Sp[kbase + tk + 32] = s1;
    }

    if (tid == 0) {
        __threadfence();
        const int d = atomicAdd(&g_done, 1);
        if (d == NBLOCKS - 1) { g_counter = 0; g_done = 0; }
    }
}

// ----------------------------------------------------------------------------
// softmax_av: grid (16 q-octets, 16 b) x 512 thr, 2 blocks/SM.
// Sums 4 partial-score buffers; warp-pair softmax; MLP-4 AV.
// ----------------------------------------------------------------------------
__global__ __launch_bounds__(512, 2) void softmax_av(
    const float* __restrict__ values,
    const int* __restrict__ valid_lens,
    float* __restrict__ out)
{
    const int b  = blockIdx.y;
    const int qo = blockIdx.x;
    const int tid = threadIdx.x;
    const int tk  = tid & 31;
    const int w   = tid >> 5;
    const int row = w >> 1;
    const int w2  = w & 1;

    __shared__ __align__(16) float attnT[128][12];
    __shared__ float pm[8][2], ps[8][2];

    const int vlen = valid_lens[b];
    const int kmax = min(KDIM, (vlen + 31) & ~31);

    const int qrow = qo * 8 + row;
    const float* S0 = &g_S[0][b][qrow][0];
    const float* S1 = &g_S[1][b][qrow][0];
    const float* S2 = &g_S[2][b][qrow][0];
    const float* S3 = &g_S[3][b][qrow][0];

    const int k0 = tk + 64 * w2;
    const int k1 = tk + 32 + 64 * w2;
    float s0 = (k0 < kmax) ? ((S0[k0] + S1[k0]) + (S2[k0] + S3[k0])) : -1e6f;
    float s1 = (k1 < kmax) ? ((S0[k1] + S1[k1]) + (S2[k1] + S3[k1])) : -1e6f;
    if (k0 >= vlen) s0 = -1e6f;
    if (k1 >= vlen) s1 = -1e6f;

    float m = fmaxf(s0, s1);
#pragma unroll
    for (int off = 16; off > 0; off >>= 1)
        m = fmaxf(m, __shfl_xor_sync(0xFFFFFFFFu, m, off));
    const float e0 = __expf(s0 - m), e1 = __expf(s1 - m);
    float sum = e0 + e1;
#pragma unroll
    for (int off = 16; off > 0; off >>= 1)
        sum += __shfl_xor_sync(0xFFFFFFFFu, sum, off);
    if (tk == 0) { pm[row][w2] = m; ps[row][w2] = sum; }
    __syncthreads();

    const float m0p = pm[row][0], m1p = pm[row][1];
    const float mg = fmaxf(m0p, m1p);
    const float sg = ps[row][0] * __expf(m0p - mg) + ps[row][1] * __expf(m1p - mg);
    const float rs = __expf(pm[row][w2] - mg) / sg;
    attnT[k0][row] = e0 * rs;
    attnT[k1][row] = e1 * rs;
    __syncthreads();

    const int d = tid;
    const float* Vb = values + b * KDIM * DDIM + d;
    float acc[8];
#pragma unroll
    for (int q = 0; q < 8; q++) acc[q] = 0.0f;

    for (int k = 0; k < kmax; k += 4) {
        const float v0 = Vb[(k + 0) * DDIM];
        const float v1 = Vb[(k + 1) * DDIM];
        const float v2 = Vb[(k + 2) * DDIM];
        const float v3 = Vb[(k + 3) * DDIM];
        float a0[8], a1[8], a2[8], a3[8];
        *(float4*)&a0[0] = *(const float4*)&attnT[k + 0][0];
        *(float4*)&a0[4] = *(const float4*)&attnT[k + 0][4];
        *(float4*)&a1[0] = *(const float4*)&attnT[k + 1][0];
        *(float4*)&a1[4] = *(const float4*)&attnT[k + 1][4];
        *(float4*)&a2[0] = *(const float4*)&attnT[k + 2][0];
        *(float4*)&a2[4] = *(const float4*)&attnT[k + 2][4];
        *(float4*)&a3[0] = *(const float4*)&attnT[k + 3][0];
        *(float4*)&a3[4] = *(const float4*)&attnT[k + 3][4];
#pragma unroll
        for (int q = 0; q < 8; q++) {
            acc[q] = fmaf(a0[q], v0, acc[q]);
            acc[q] = fmaf(a1[q], v1, acc[q]);
            acc[q] = fmaf(a2[q], v2, acc[q]);
            acc[q] = fmaf(a3[q], v3, acc[q]);
        }
    }

    float* Ob = out + (b * QDIM + qo * 8) * DDIM + d;
#pragma unroll
    for (int q = 0; q < 8; q++)
        Ob[q * DDIM] = acc[q];
}

// ----------------------------------------------------------------------------
extern "C" void kernel_launch(void* const* d_in, const int* in_sizes, int n_in,
                              void* d_out, int out_size)
{
    const float* queries    = (const float*)d_in[0];
    const float* keys       = (const float*)d_in[1];
    const float* values     = (const float*)d_in[2];
    const int*   valid_lens = (const int*)d_in[3];
    const float* Wq         = (const float*)d_in[4];
    const float* Wk         = (const float*)d_in[5];
    const float* wv         = (const float*)d_in[6];
    float* out = (float*)d_out;

    prep<<<dim3(256, 2), 256>>>(Wq, Wk);
    bf16_gemm<<<dim3(4, 16, 2), 256>>>(queries, keys);
    score_kernel<<<NBLOCKS, 512>>>(valid_lens, wv);
    softmax_av<<<dim3(16, 16), 512>>>(values, valid_lens, out);
}